// round 14
// baseline (speedup 1.0000x reference)
#include <cuda_runtime.h>
#include <cuda_bf16.h>
#include <cstdint>

typedef unsigned long long u64;
typedef unsigned int u32;
typedef unsigned short u16;

// ---------------- packed fp32x2 helpers (attention kernel) ----------------
__device__ __forceinline__ u64 pack2(float x, float y) {
    u64 r; asm("mov.b64 %0, {%1, %2};" : "=l"(r) : "f"(x), "f"(y)); return r;
}
__device__ __forceinline__ float2 unpack2(u64 v) {
    float2 r; asm("mov.b64 {%0, %1}, %2;" : "=f"(r.x), "=f"(r.y) : "l"(v)); return r;
}
__device__ __forceinline__ void fma2(u64& d, u64 a, u64 b) {
    asm("fma.rn.f32x2 %0, %1, %2, %0;" : "+l"(d) : "l"(a), "l"(b));
}
__device__ __forceinline__ u64 mul2(u64 a, u64 b) {
    u64 d; asm("mul.rn.f32x2 %0, %1, %2;" : "=l"(d) : "l"(a), "l"(b)); return d;
}
__device__ __forceinline__ u64 add2(u64 a, u64 b) {
    u64 d; asm("add.rn.f32x2 %0, %1, %2;" : "=l"(d) : "l"(a), "l"(b)); return d;
}

// ---------------- bf16 helpers ----------------
__device__ __forceinline__ u32 packbf(float v0, float v1) {
    u32 r; asm("cvt.rn.bf16x2.f32 %0, %1, %2;" : "=r"(r) : "f"(v1), "f"(v0));
    return r;
}
__device__ __forceinline__ float bf_lo_f(u32 w) { return __uint_as_float(w << 16); }
__device__ __forceinline__ float bf_hi_f(u32 w) { return __uint_as_float(w & 0xffff0000u); }

// m16n8k16 bf16 MMA, row.col, fp32 accumulate
__device__ __forceinline__ void mma16(float* c, u32 a0, u32 a1, u32 a2, u32 a3,
                                      u32 b0, u32 b1) {
    asm volatile("mma.sync.aligned.m16n8k16.row.col.f32.bf16.bf16.f32 "
                 "{%0,%1,%2,%3}, {%4,%5,%6,%7}, {%8,%9}, {%0,%1,%2,%3};"
                 : "+f"(c[0]), "+f"(c[1]), "+f"(c[2]), "+f"(c[3])
                 : "r"(a0), "r"(a1), "r"(a2), "r"(a3), "r"(b0), "r"(b1));
}

// ---------------- cp.async / ldmatrix ----------------
__device__ __forceinline__ u32 smem_u32(const void* p) {
    u32 a; asm("{ .reg .u64 t; cvta.to.shared.u64 t, %1; cvt.u32.u64 %0, t; }"
                : "=r"(a) : "l"(p));
    return a;
}
__device__ __forceinline__ void cpasync16(u32 dst, const void* src, int srcsize) {
    asm volatile("cp.async.cg.shared.global [%0], [%1], 16, %2;"
                 :: "r"(dst), "l"(src), "r"(srcsize) : "memory");
}
__device__ __forceinline__ void cpcommit() {
    asm volatile("cp.async.commit_group;" ::: "memory");
}
template<int N> __device__ __forceinline__ void cpwait() {
    asm volatile("cp.async.wait_group %0;" :: "n"(N) : "memory");
}
__device__ __forceinline__ void ldsm4(u32& r0, u32& r1, u32& r2, u32& r3, u32 addr) {
    asm volatile("ldmatrix.sync.aligned.m8n8.x4.shared.b16 {%0,%1,%2,%3}, [%4];"
                 : "=r"(r0), "=r"(r1), "=r"(r2), "=r"(r3) : "r"(addr));
}

// ---------------- scratch (device globals: allocation-free) ----------------
__device__ float g_Qt[4096 * 1024];
__device__ float g_Qd[4096 * 1024];
__device__ float g_Kt[1024 * 1024];
__device__ float g_Vt[1024 * 1024];
__device__ float g_Kd[1024 * 1024];
__device__ float g_Vd[1024 * 1024];
__device__ float g_H [4096 * 1024];
__device__ float g_gate[4096];
__device__ u16 g_trH[4096 * 1024], g_trL[4096 * 1024];
__device__ u16 g_deH[4096 * 1024], g_deL[4096 * 1024];
__device__ u16 g_pTH[1000 * 4096], g_pTL[1000 * 4096];
__device__ u16 g_pDH[1000 * 4096], g_pDL[1000 * 4096];
__device__ u16 g_ctH[4096 * 1024], g_ctL[4096 * 1024];   // gate-scaled context
__device__ u16 g_cdH[4096 * 1024], g_cdL[4096 * 1024];
__device__ u16 g_wqtH[1024 * 1024], g_wqtL[1024 * 1024];
__device__ u16 g_wqdH[1024 * 1024], g_wqdL[1024 * 1024];
__device__ u16 g_wktH[1024 * 4096], g_wktL[1024 * 4096];
__device__ u16 g_wvtH[1024 * 4096], g_wvtL[1024 * 4096];
__device__ u16 g_wkdH[1024 * 4096], g_wkdL[1024 * 4096];
__device__ u16 g_wvdH[1024 * 4096], g_wvdL[1024 * 4096];
__device__ u16 g_woH[4096 * 2048], g_woL[4096 * 2048];   // fused [Wot | Wod], [N,2K]
__device__ u16 g_gw1H[1024 * 2048], g_gw1L[1024 * 2048];

// ---------------- pre-pass: elementwise fp32 -> bf16 hi/lo ----------------
struct CArg { const float* src[4]; u32* dH[4]; u32* dL[4]; int n2[4]; };
__global__ __launch_bounds__(256)
void convA(CArg c)
{
    int z = blockIdx.y;
    int i = blockIdx.x * 256 + threadIdx.x;
    if (i >= c.n2[z]) return;
    float2 v = ((const float2*)c.src[z])[i];
    u32 hw = packbf(v.x, v.y);
    float l0 = v.x - bf_lo_f(hw);
    float l1 = v.y - bf_hi_f(hw);
    c.dH[z][i] = hw;
    c.dL[z][i] = packbf(l0, l1);
}

// ---------------- pre-pass: transpose [K,N] fp32 -> [N, ldk] bf16 hi/lo -----
struct TArg {
    const float* src[9]; u16* dH[9]; u16* dL[9];
    int K[9]; int N[9]; int ldk[9]; int koff[9];
};
__global__ __launch_bounds__(256)
void convB(TArg t)
{
    __shared__ float tile[32][33];
    int z = blockIdx.z;
    int K = t.K[z], N = t.N[z], ldk = t.ldk[z], koff = t.koff[z];
    int k0 = blockIdx.x * 32, n0 = blockIdx.y * 32;
    if (k0 >= K || n0 >= N) return;
    const float* src = t.src[z];
    #pragma unroll
    for (int r = 0; r < 4; r++)
        tile[threadIdx.y + r * 8][threadIdx.x] =
            src[(size_t)(k0 + threadIdx.y + r * 8) * N + n0 + threadIdx.x];
    __syncthreads();
    u16* dH = t.dH[z]; u16* dL = t.dL[z];
    #pragma unroll
    for (int r = 0; r < 4; r++) {
        int n = n0 + threadIdx.y + r * 8;
        int k = k0 + threadIdx.x;
        float v = tile[threadIdx.x][threadIdx.y + r * 8];
        __nv_bfloat16 h = __float2bfloat16(v);
        float hf = __bfloat162float(h);
        __nv_bfloat16 l = __float2bfloat16(v - hf);
        dH[(size_t)n * ldk + koff + k] = *(u16*)&h;
        dL[(size_t)n * ldk + koff + k] = *(u16*)&l;
    }
}

// ---------------- segment-dispatch GEMM argument block ----------------
struct Seg {
    const u16 *AH, *AL, *A2H, *A2L, *BH, *BL;
    const float *bias, *bias2;
    float* C;
    int M, N, K, Ksp, epi, gx, blk0;
};
struct MArg { Seg s[7]; int nseg; const float* gate; };

// ---------------- HMMA 3xBF16 GEMM: k32 stages, 2-buffer ring, segments -----
static constexpr int ROWB   = 80;
static constexpr int PLANEB = 128 * ROWB;        // 10240
static constexpr int STAGEB = 4 * PLANEB;        // 40960
static constexpr int SMEM_DYN = 2 * STAGEB;      // 81920

__global__ __launch_bounds__(256, 2)
void tgemm(MArg m)
{
    extern __shared__ __align__(16) char smem[];
    const u32 sb = smem_u32(smem);

    const int tid  = threadIdx.x;
    const int wid  = tid >> 5;
    const int lane = tid & 31;
    const int gq   = lane >> 2;
    const int tq   = lane & 3;
    const int wr   = (wid & 1) * 64;
    const int wc   = (wid >> 1) * 32;

    const int bid = blockIdx.x;
    int si = 0;
    #pragma unroll
    for (int i = 1; i < 7; i++)
        if (i < m.nseg && bid >= m.s[i].blk0) si = i;
    const u16* __restrict__ AH  = m.s[si].AH;
    const u16* __restrict__ AL  = m.s[si].AL;
    const u16* __restrict__ A2H = m.s[si].A2H;
    const u16* __restrict__ A2L = m.s[si].A2L;
    const u16* __restrict__ BH  = m.s[si].BH;
    const u16* __restrict__ BL  = m.s[si].BL;
    const float* __restrict__ bias  = m.s[si].bias;
    const float* __restrict__ bias2 = m.s[si].bias2;
    float* __restrict__ C = m.s[si].C;
    const int M = m.s[si].M, N = m.s[si].N, K = m.s[si].K, Ksp = m.s[si].Ksp;
    const int epi = m.s[si].epi;
    const int local = bid - m.s[si].blk0;
    const int gx = m.s[si].gx;
    const int row0 = (local / gx) * 128;
    const int col0 = (local % gx) * 128;

    float acc[4][4][4];
    #pragma unroll
    for (int i = 0; i < 4; i++)
        #pragma unroll
        for (int j = 0; j < 4; j++)
            #pragma unroll
            for (int q = 0; q < 4; q++) acc[i][j][q] = 0.f;

    auto issue = [&](int s, int buf) {
        const int k0 = s * 32;
        #pragma unroll
        for (int it = 0; it < 2; it++) {
            int c = it * 256 + tid;
            int r = c >> 2, q = c & 3;
            const u32 dst = sb + buf * STAGEB + r * ROWB + q * 16;
            int kk = k0 + q * 8;
            {
                const u16* bh = AH; const u16* bl = AL;
                int ka = kk;
                if (ka >= Ksp) { bh = A2H; bl = A2L; ka -= Ksp; }
                int gr = row0 + r;
                int ok = (gr < M) ? 16 : 0;
                int grc = (gr < M) ? gr : (M - 1);
                cpasync16(dst,          bh + (size_t)grc * Ksp + ka, ok);
                cpasync16(dst + PLANEB, bl + (size_t)grc * Ksp + ka, ok);
            }
            {
                size_t off = (size_t)(col0 + r) * K + kk;
                cpasync16(dst + 2 * PLANEB, BH + off, 16);
                cpasync16(dst + 3 * PLANEB, BL + off, 16);
            }
        }
    };

    const int lr = lane & 7;
    const int lb = (lane >> 3) & 1;
    const int lh = lane >> 4;
    const u32 aoff = (u32)((wr + lb * 8 + lr) * ROWB + lh * 16);
    const u32 boff = (u32)((wc + lh * 8 + lr) * ROWB + lb * 16) + 2 * PLANEB;

    auto compute = [&](int buf) {
        const u32 base = sb + buf * STAGEB;
        #pragma unroll
        for (int kc = 0; kc < 2; kc++) {
            const u32 ka = base + aoff + kc * 32;
            const u32 kb = base + boff + kc * 32;
            u32 ah[4][4], bh[4][2], bl[4][2];
            #pragma unroll
            for (int mi = 0; mi < 4; mi++)
                ldsm4(ah[mi][0], ah[mi][1], ah[mi][2], ah[mi][3],
                      ka + mi * (16 * ROWB));
            #pragma unroll
            for (int nj = 0; nj < 2; nj++)
                ldsm4(bh[2 * nj][0], bh[2 * nj][1], bh[2 * nj + 1][0], bh[2 * nj + 1][1],
                      kb + nj * (16 * ROWB));
            #pragma unroll
            for (int mi = 0; mi < 4; mi++)
                #pragma unroll
                for (int ni = 0; ni < 4; ni++)
                    mma16(acc[mi][ni], ah[mi][0], ah[mi][1], ah[mi][2], ah[mi][3],
                          bh[ni][0], bh[ni][1]);
            #pragma unroll
            for (int nj = 0; nj < 2; nj++)
                ldsm4(bl[2 * nj][0], bl[2 * nj][1], bl[2 * nj + 1][0], bl[2 * nj + 1][1],
                      kb + PLANEB + nj * (16 * ROWB));
            #pragma unroll
            for (int mi = 0; mi < 4; mi++)
                #pragma unroll
                for (int ni = 0; ni < 4; ni++)
                    mma16(acc[mi][ni], ah[mi][0], ah[mi][1], ah[mi][2], ah[mi][3],
                          bl[ni][0], bl[ni][1]);
            #pragma unroll
            for (int mi = 0; mi < 4; mi++)      // reuse ah regs for Al
                ldsm4(ah[mi][0], ah[mi][1], ah[mi][2], ah[mi][3],
                      ka + PLANEB + mi * (16 * ROWB));
            #pragma unroll
            for (int mi = 0; mi < 4; mi++)
                #pragma unroll
                for (int ni = 0; ni < 4; ni++)
                    mma16(acc[mi][ni], ah[mi][0], ah[mi][1], ah[mi][2], ah[mi][3],
                          bh[ni][0], bh[ni][1]);
        }
    };

    const int nst = K / 32;
    issue(0, 0);
    cpcommit();

    for (int s = 0; s < nst; s++) {
        cpwait<0>();
        __syncthreads();
        if (s + 1 < nst) issue(s + 1, (s + 1) & 1);
        cpcommit();
        compute(s & 1);
    }

    #pragma unroll
    for (int mi = 0; mi < 4; mi++) {
        #pragma unroll
        for (int rr = 0; rr < 2; rr++) {
            int r = row0 + wr + mi * 16 + gq + rr * 8;
            if (r >= M) continue;
            float gg = (epi == 4) ? m.gate[r] : 0.f;
            #pragma unroll
            for (int ni = 0; ni < 4; ni++) {
                int c = col0 + wc + ni * 8 + tq * 2;
                size_t idx = (size_t)r * N + c;
                float a0 = acc[mi][ni][rr * 2 + 0];
                float a1 = acc[mi][ni][rr * 2 + 1];
                float2 o;
                if (epi == 0) {
                    o = make_float2(a0 + bias[c], a1 + bias[c + 1]);
                } else if (epi == 1) {
                    o = make_float2(fmaxf(a0 + bias[c], 0.f),
                                    fmaxf(a1 + bias[c + 1], 0.f));
                } else {
                    o = make_float2(
                        a0 + gg * bias[c]     + (1.f - gg) * bias2[c],
                        a1 + gg * bias[c + 1] + (1.f - gg) * bias2[c + 1]);
                }
                *(float2*)(C + idx) = o;
            }
        }
    }
}

// ---------------- flash attention: 128 rows/block, shared 64-key K/V tiles --
// Dynamic smem: Ks u64[2048] | Vs u64[2048] | Ss float[64*128]  = 64 KB
static constexpr int FA_SMEM = 16384 + 16384 + 32768;

struct FArg {
    const float* Q[2];
    const float* Kb[2];
    const float* Vb[2];
    u32* OH[2];
    u32* OL[2];
};

__global__ __launch_bounds__(128)
void flash_attn(FArg f, int S, const float* __restrict__ G)
{
    extern __shared__ __align__(16) char fsm[];
    u64*   Ks = (u64*)fsm;                    // [64*32]
    u64*   Vs = (u64*)(fsm + 16384);          // [64*32]
    float* Ss = (float*)(fsm + 32768);        // [64][128]

    const int tid = threadIdx.x;
    const int h   = blockIdx.y;
    const int sel = blockIdx.z >> 3;
    const int b   = blockIdx.z & 7;
    const int row = b * 512 + blockIdx.x * 128 + tid;

    const float* __restrict__ Q  = f.Q[sel];
    const float* __restrict__ Kb = f.Kb[sel];
    const float* __restrict__ Vb = f.Vb[sel];

    const u64* qp = (const u64*)(Q + (size_t)row * 1024 + h * 64);
    u64 q2[32];
    #pragma unroll
    for (int i = 0; i < 32; i++) q2[i] = qp[i];

    u64 acc2[32] = {};
    float m = -1e30f, lsum = 0.f;
    const float scale = 0.125f;

    for (int s0 = 0; s0 < S; s0 += 64) {
        int jmax = S - s0; if (jmax > 64) jmax = 64;
        #pragma unroll
        for (int i = 0; i < 16; i++) {
            int idx = i * 128 + tid;          // 0..2047
            int j = idx >> 5, e2 = idx & 31;
            int srow = s0 + j;
            u64 kv = 0, vv = 0;
            if (srow < S) {
                kv = ((const u64*)(Kb + (size_t)srow * 1024 + h * 64))[e2];
                vv = ((const u64*)(Vb + (size_t)srow * 1024 + h * 64))[e2];
            }
            Ks[idx] = kv; Vs[idx] = vv;
        }
        __syncthreads();

        float tmax = -1e30f;
        for (int j = 0; j < 64; j++) {
            float s;
            if (j < jmax) {
                u64 sa = 0, sb = 0, sc = 0, sd = 0;
                const ulonglong2* kp = (const ulonglong2*)&Ks[j * 32];
                #pragma unroll
                for (int e = 0; e < 8; e++) {
                    ulonglong2 kv1 = kp[e * 2];
                    ulonglong2 kv2 = kp[e * 2 + 1];
                    fma2(sa, q2[e * 4 + 0], kv1.x);
                    fma2(sb, q2[e * 4 + 1], kv1.y);
                    fma2(sc, q2[e * 4 + 2], kv2.x);
                    fma2(sd, q2[e * 4 + 3], kv2.y);
                }
                u64 sab = add2(sa, sb);
                u64 scd = add2(sc, sd);
                float2 sf = unpack2(add2(sab, scd));
                s = (sf.x + sf.y) * scale;
            } else {
                s = -1e30f;
            }
            tmax = fmaxf(tmax, s);
            Ss[j * 128 + tid] = s;
        }

        float mnew  = fmaxf(m, tmax);
        float alpha = __expf(m - mnew);
        lsum *= alpha;
        u64 a2 = pack2(alpha, alpha);
        #pragma unroll
        for (int e = 0; e < 32; e++) acc2[e] = mul2(acc2[e], a2);

        for (int j = 0; j < 64; j++) {
            float p = __expf(Ss[j * 128 + tid] - mnew);
            lsum += p;
            u64 p2 = pack2(p, p);
            const ulonglong2* vp = (const ulonglong2*)&Vs[j * 32];
            #pragma unroll
            for (int e = 0; e < 16; e++) {
                ulonglong2 vv = vp[e];
                fma2(acc2[e * 2],     p2, vv.x);
                fma2(acc2[e * 2 + 1], p2, vv.y);
            }
        }
        m = mnew;
        __syncthreads();
    }

    float gv = G[row];
    float gs = (sel == 0) ? gv : (1.f - gv);
    float inv = gs / lsum;
    u32* OH = f.OH[sel];
    u32* OL = f.OL[sel];
    size_t obase = (size_t)row * 512 + h * 32;
    #pragma unroll
    for (int e = 0; e < 32; e++) {
        float2 v = unpack2(acc2[e]);
        v.x *= inv; v.y *= inv;
        u32 hw = packbf(v.x, v.y);
        float l0 = v.x - bf_lo_f(hw);
        float l1 = v.y - bf_hi_f(hw);
        OH[obase + e] = hw;
        OL[obase + e] = packbf(l0, l1);
    }
}

// ---------------- gate: G[r] = sigmoid(H[r,:] . W2 + b2), one warp per row ----
__global__ __launch_bounds__(256)
void gate_kernel(const float* __restrict__ H, const float* __restrict__ W2,
                 const float* __restrict__ b2, float* __restrict__ G)
{
    int w = (blockIdx.x * blockDim.x + threadIdx.x) >> 5;
    int lane = threadIdx.x & 31;
    const float* hp = H + (size_t)w * 1024;
    float s = 0.f;
    #pragma unroll
    for (int i = 0; i < 32; i++) s += hp[lane + i * 32] * W2[lane + i * 32];
    #pragma unroll
    for (int o = 16; o; o >>= 1) s += __shfl_xor_sync(0xffffffffu, s, o);
    if (lane == 0) G[w] = 1.f / (1.f + __expf(-(s + b2[0])));
}

// ---------------- launch ----------------
extern "C" void kernel_launch(void* const* d_in, const int* in_sizes, int n_in,
                              void* d_out, int out_size)
{
    const float* trend  = (const float*)d_in[0];
    const float* detail = (const float*)d_in[1];
    const float* protoT = (const float*)d_in[2];
    const float* protoD = (const float*)d_in[3];
    const float* tWq = (const float*)d_in[4];  const float* tbq = (const float*)d_in[5];
    const float* tWk = (const float*)d_in[6];  const float* tbk = (const float*)d_in[7];
    const float* tWv = (const float*)d_in[8];  const float* tbv = (const float*)d_in[9];
    const float* tWo = (const float*)d_in[10]; const float* tbo = (const float*)d_in[11];
    const float* dWq = (const float*)d_in[12]; const float* dbq = (const float*)d_in[13];
    const float* dWk = (const float*)d_in[14]; const float* dbk = (const float*)d_in[15];
    const float* dWv = (const float*)d_in[16]; const float* dbv = (const float*)d_in[17];
    const float* dWo = (const float*)d_in[18]; const float* dbo = (const float*)d_in[19];
    const float* gW1 = (const float*)d_in[20]; const float* gb1 = (const float*)d_in[21];
    const float* gW2 = (const float*)d_in[22]; const float* gb2 = (const float*)d_in[23];
    float* out = (float*)d_out;

    #define SYM(T, v, s) T* v; cudaGetSymbolAddress((void**)&v, s)
    SYM(float, Qt, g_Qt);   SYM(float, Qd, g_Qd);
    SYM(float, Kt, g_Kt);   SYM(float, Vt, g_Vt);
    SYM(float, Kd, g_Kd);   SYM(float, Vd, g_Vd);
    SYM(float, H,  g_H);    SYM(float, G,  g_gate);
    SYM(u16, trH, g_trH);   SYM(u16, trL, g_trL);
    SYM(u16, deH, g_deH);   SYM(u16, deL, g_deL);
    SYM(u16, pTH, g_pTH);   SYM(u16, pTL, g_pTL);
    SYM(u16, pDH, g_pDH);   SYM(u16, pDL, g_pDL);
    SYM(u16, ctH, g_ctH);   SYM(u16, ctL, g_ctL);
    SYM(u16, cdH, g_cdH);   SYM(u16, cdL, g_cdL);
    SYM(u16, wqtH, g_wqtH); SYM(u16, wqtL, g_wqtL);
    SYM(u16, wqdH, g_wqdH); SYM(u16, wqdL, g_wqdL);
    SYM(u16, wktH, g_wktH); SYM(u16, wktL, g_wktL);
    SYM(u16, wvtH, g_wvtH); SYM(u16, wvtL, g_wvtL);
    SYM(u16, wkdH, g_wkdH); SYM(u16, wkdL, g_wkdL);
    SYM(u16, wvdH, g_wvdH); SYM(u16, wvdL, g_wvdL);
    SYM(u16, woH, g_woH);   SYM(u16, woL, g_woL);
    SYM(u16, gw1H, g_gw1H); SYM(u16, gw1L, g_gw1L);
    #undef SYM

    cudaFuncSetAttribute(tgemm, cudaFuncAttributeMaxDynamicSharedMemorySize, SMEM_DYN);
    cudaFuncSetAttribute(flash_attn, cudaFuncAttributeMaxDynamicSharedMemorySize, FA_SMEM);

    // 0a) A-side conversions
    {
        CArg c = {};
        c.src[0] = trend;  c.dH[0] = (u32*)trH; c.dL[0] = (u32*)trL; c.n2[0] = 4096 * 512;
        c.src[1] = detail; c.dH[1] = (u32*)deH; c.dL[1] = (u32*)deL; c.n2[1] = 4096 * 512;
        c.src[2] = protoT; c.dH[2] = (u32*)pTH; c.dL[2] = (u32*)pTL; c.n2[2] = 1000 * 2048;
        c.src[3] = protoD; c.dH[3] = (u32*)pDH; c.dL[3] = (u32*)pDL; c.n2[3] = 1000 * 2048;
        convA<<<dim3(8192, 4), 256>>>(c);
    }
    // 0b) weight transpose+split
    {
        TArg t = {};
        int i = 0;
        auto add = [&](const float* s, u16* h, u16* l, int K, int N, int ldk, int koff) {
            t.src[i] = s; t.dH[i] = h; t.dL[i] = l;
            t.K[i] = K; t.N[i] = N; t.ldk[i] = ldk; t.koff[i] = koff; i++;
        };
        add(tWq, wqtH, wqtL, 1024, 1024, 1024, 0);
        add(dWq, wqdH, wqdL, 1024, 1024, 1024, 0);
        add(tWk, wktH, wktL, 4096, 1024, 4096, 0);
        add(tWv, wvtH, wvtL, 4096, 1024, 4096, 0);
        add(dWk, wkdH, wkdL, 4096, 1024, 4096, 0);
        add(dWv, wvdH, wvdL, 4096, 1024, 4096, 0);
        add(tWo, woH,  woL,  1024, 4096, 2048, 0);
        add(dWo, woH,  woL,  1024, 4096, 2048, 1024);
        add(gW1, gw1H, gw1L, 2048, 1024, 2048, 0);
        convB<<<dim3(128, 128, 9), dim3(32, 8)>>>(t);
    }

    // 1) merged pre-attention GEMMs (1024 CTAs)
    {
        MArg a = {};
        int blk = 0, i = 0;
        auto seg = [&](const u16* ah, const u16* al, const u16* a2h, const u16* a2l,
                       const u16* bh, const u16* bl, const float* bi, float* c,
                       int M, int N, int K, int ksp, int epi) {
            Seg& s = a.s[i++];
            s.AH = ah; s.AL = al; s.A2H = a2h; s.A2L = a2l; s.BH = bh; s.BL = bl;
            s.bias = bi; s.bias2 = nullptr; s.C = c;
            s.M = M; s.N = N; s.K = K; s.Ksp = ksp; s.epi = epi;
            s.gx = N / 128; s.blk0 = blk;
            blk += (N / 128) * ((M + 127) / 128);
        };
        seg(trH, trL, deH, deL, gw1H, gw1L, gb1, H, 4096, 1024, 2048, 1024, 1);
        seg(trH, trL, trH, trL, wqtH, wqtL, tbq, Qt, 4096, 1024, 1024, 1024, 0);
        seg(deH, deL, deH, deL, wqdH, wqdL, dbq, Qd, 4096, 1024, 1024, 1024, 0);
        seg(pTH, pTL, pTH, pTL, wktH, wktL, tbk, Kt, 1000, 1024, 4096, 4096, 0);
        seg(pTH, pTL, pTH, pTL, wvtH, wvtL, tbv, Vt, 1000, 1024, 4096, 4096, 0);
        seg(pDH, pDL, pDH, pDL, wkdH, wkdL, dbk, Kd, 1000, 1024, 4096, 4096, 0);
        seg(pDH, pDL, pDH, pDL, wvdH, wvdL, dbv, Vd, 1000, 1024, 4096, 4096, 0);
        a.nseg = i;
        a.gate = G;
        tgemm<<<blk, 256, SMEM_DYN>>>(a);
    }
    // 2) gate
    gate_kernel<<<512, 256>>>(H, gW2, gb2, G);

    // 3) attention (128 rows/block, gate-scaled bf16 hi/lo output)
    {
        FArg fa = {};
        fa.Q[0] = Qt; fa.Kb[0] = Kt; fa.Vb[0] = Vt; fa.OH[0] = (u32*)ctH; fa.OL[0] = (u32*)ctL;
        fa.Q[1] = Qd; fa.Kb[1] = Kd; fa.Vb[1] = Vd; fa.OH[1] = (u32*)cdH; fa.OL[1] = (u32*)cdL;
        flash_attn<<<dim3(4, 16, 16), 128, FA_SMEM>>>(fa, 1000, G);
    }
    // 4) merged output projection + blend (single segment, epi 4)
    {
        MArg a = {};
        Seg& s = a.s[0];
        s.AH = ctH; s.AL = ctL; s.A2H = cdH; s.A2L = cdL;
        s.BH = woH; s.BL = woL;
        s.bias = tbo; s.bias2 = dbo; s.C = out;
        s.M = 4096; s.N = 4096; s.K = 2048; s.Ksp = 1024; s.epi = 4;
        s.gx = 32; s.blk0 = 0;
        a.nseg = 1;
        a.gate = G;
        tgemm<<<1024, 256, SMEM_DYN>>>(a);
    }

    (void)in_sizes; (void)n_in; (void)out_size;
}

// round 15
// speedup vs baseline: 1.2836x; 1.2836x over previous
#include <cuda_runtime.h>
#include <cuda_bf16.h>
#include <cstdint>

typedef unsigned long long u64;
typedef unsigned int u32;
typedef unsigned short u16;

// ---------------- packed fp32x2 helpers ----------------
__device__ __forceinline__ u64 pack2(float x, float y) {
    u64 r; asm("mov.b64 %0, {%1, %2};" : "=l"(r) : "f"(x), "f"(y)); return r;
}
__device__ __forceinline__ float2 unpack2(u64 v) {
    float2 r; asm("mov.b64 {%0, %1}, %2;" : "=f"(r.x), "=f"(r.y) : "l"(v)); return r;
}
__device__ __forceinline__ void fma2(u64& d, u64 a, u64 b) {
    asm("fma.rn.f32x2 %0, %1, %2, %0;" : "+l"(d) : "l"(a), "l"(b));
}
__device__ __forceinline__ u64 mul2(u64 a, u64 b) {
    u64 d; asm("mul.rn.f32x2 %0, %1, %2;" : "=l"(d) : "l"(a), "l"(b)); return d;
}

// ---------------- bf16 helpers ----------------
__device__ __forceinline__ u32 packbf(float v0, float v1) {
    u32 r; asm("cvt.rn.bf16x2.f32 %0, %1, %2;" : "=r"(r) : "f"(v1), "f"(v0));
    return r;
}
__device__ __forceinline__ float bf_lo_f(u32 w) { return __uint_as_float(w << 16); }
__device__ __forceinline__ float bf_hi_f(u32 w) { return __uint_as_float(w & 0xffff0000u); }

// m16n8k16 bf16 MMA, row.col, fp32 accumulate
__device__ __forceinline__ void mma16(float* c, u32 a0, u32 a1, u32 a2, u32 a3,
                                      u32 b0, u32 b1) {
    asm volatile("mma.sync.aligned.m16n8k16.row.col.f32.bf16.bf16.f32 "
                 "{%0,%1,%2,%3}, {%4,%5,%6,%7}, {%8,%9}, {%0,%1,%2,%3};"
                 : "+f"(c[0]), "+f"(c[1]), "+f"(c[2]), "+f"(c[3])
                 : "r"(a0), "r"(a1), "r"(a2), "r"(a3), "r"(b0), "r"(b1));
}

// ---------------- cp.async / ldmatrix ----------------
__device__ __forceinline__ u32 smem_u32(const void* p) {
    u32 a; asm("{ .reg .u64 t; cvta.to.shared.u64 t, %1; cvt.u32.u64 %0, t; }"
                : "=r"(a) : "l"(p));
    return a;
}
__device__ __forceinline__ void cpasync16(u32 dst, const void* src, int srcsize) {
    asm volatile("cp.async.cg.shared.global [%0], [%1], 16, %2;"
                 :: "r"(dst), "l"(src), "r"(srcsize) : "memory");
}
__device__ __forceinline__ void cpcommit() {
    asm volatile("cp.async.commit_group;" ::: "memory");
}
template<int N> __device__ __forceinline__ void cpwait() {
    asm volatile("cp.async.wait_group %0;" :: "n"(N) : "memory");
}
__device__ __forceinline__ void ldsm4(u32& r0, u32& r1, u32& r2, u32& r3, u32 addr) {
    asm volatile("ldmatrix.sync.aligned.m8n8.x4.shared.b16 {%0,%1,%2,%3}, [%4];"
                 : "=r"(r0), "=r"(r1), "=r"(r2), "=r"(r3) : "r"(addr));
}

// ---------------- scratch (device globals: allocation-free) ----------------
__device__ float g_Vt[1024 * 1024];
__device__ float g_Vd[1024 * 1024];
__device__ float g_H [4096 * 1024];
__device__ float g_gate[4096];
__device__ u16 g_QtH[4096 * 1024], g_QtL[4096 * 1024];
__device__ u16 g_QdH[4096 * 1024], g_QdL[4096 * 1024];
__device__ u16 g_KtH[1024 * 1024], g_KtL[1024 * 1024];
__device__ u16 g_KdH[1024 * 1024], g_KdL[1024 * 1024];
__device__ u16 g_trH[4096 * 1024], g_trL[4096 * 1024];
__device__ u16 g_deH[4096 * 1024], g_deL[4096 * 1024];
__device__ u16 g_pTH[1000 * 4096], g_pTL[1000 * 4096];
__device__ u16 g_pDH[1000 * 4096], g_pDL[1000 * 4096];
__device__ u16 g_ctH[4096 * 1024], g_ctL[4096 * 1024];
__device__ u16 g_cdH[4096 * 1024], g_cdL[4096 * 1024];
__device__ u16 g_wqtH[1024 * 1024], g_wqtL[1024 * 1024];
__device__ u16 g_wqdH[1024 * 1024], g_wqdL[1024 * 1024];
__device__ u16 g_wktH[1024 * 4096], g_wktL[1024 * 4096];
__device__ u16 g_wvtH[1024 * 4096], g_wvtL[1024 * 4096];
__device__ u16 g_wkdH[1024 * 4096], g_wkdL[1024 * 4096];
__device__ u16 g_wvdH[1024 * 4096], g_wvdL[1024 * 4096];
__device__ u16 g_woH[4096 * 2048], g_woL[4096 * 2048];
__device__ u16 g_gw1H[1024 * 2048], g_gw1L[1024 * 2048];

// ---------------- pre-pass: elementwise fp32 -> bf16 hi/lo ----------------
struct CArg { const float* src[4]; u32* dH[4]; u32* dL[4]; int n2[4]; };
__global__ __launch_bounds__(256)
void convA(CArg c)
{
    int z = blockIdx.y;
    int i = blockIdx.x * 256 + threadIdx.x;
    if (i >= c.n2[z]) return;
    float2 v = ((const float2*)c.src[z])[i];
    u32 hw = packbf(v.x, v.y);
    float l0 = v.x - bf_lo_f(hw);
    float l1 = v.y - bf_hi_f(hw);
    c.dH[z][i] = hw;
    c.dL[z][i] = packbf(l0, l1);
}

// ---------------- pre-pass: transpose [K,N] fp32 -> [N, ldk] bf16 hi/lo -----
struct TArg {
    const float* src[9]; u16* dH[9]; u16* dL[9];
    int K[9]; int N[9]; int ldk[9]; int koff[9];
};
__global__ __launch_bounds__(256)
void convB(TArg t)
{
    __shared__ float tile[32][33];
    int z = blockIdx.z;
    int K = t.K[z], N = t.N[z], ldk = t.ldk[z], koff = t.koff[z];
    int k0 = blockIdx.x * 32, n0 = blockIdx.y * 32;
    if (k0 >= K || n0 >= N) return;
    const float* src = t.src[z];
    #pragma unroll
    for (int r = 0; r < 4; r++)
        tile[threadIdx.y + r * 8][threadIdx.x] =
            src[(size_t)(k0 + threadIdx.y + r * 8) * N + n0 + threadIdx.x];
    __syncthreads();
    u16* dH = t.dH[z]; u16* dL = t.dL[z];
    #pragma unroll
    for (int r = 0; r < 4; r++) {
        int n = n0 + threadIdx.y + r * 8;
        int k = k0 + threadIdx.x;
        float v = tile[threadIdx.x][threadIdx.y + r * 8];
        __nv_bfloat16 h = __float2bfloat16(v);
        float hf = __bfloat162float(h);
        __nv_bfloat16 l = __float2bfloat16(v - hf);
        dH[(size_t)n * ldk + koff + k] = *(u16*)&h;
        dL[(size_t)n * ldk + koff + k] = *(u16*)&l;
    }
}

// ---------------- segment-dispatch GEMM argument block ----------------
// epi 0: C(fp32) = AB + bias
// epi 1: C(fp32) = relu(AB + bias)
// epi 2: CH/CL(bf16 hi/lo planes) = AB + bias
// epi 4: C(fp32) = AB + g[r]*bias[c] + (1-g[r])*bias2[c]
struct Seg {
    const u16 *AH, *AL, *A2H, *A2L, *BH, *BL;
    const float *bias, *bias2;
    float* C;
    u16 *CH, *CL;
    int M, N, K, Ksp, epi, gx, blk0;
};
struct MArg { Seg s[7]; int nseg; const float* gate; };

// ---------------- HMMA 3xBF16 GEMM: k32 stages, 2-buffer ring, segments -----
static constexpr int ROWB   = 80;
static constexpr int PLANEB = 128 * ROWB;
static constexpr int STAGEB = 4 * PLANEB;
static constexpr int SMEM_DYN = 2 * STAGEB;      // 81920

__global__ __launch_bounds__(256, 2)
void tgemm(MArg m)
{
    extern __shared__ __align__(16) char smem[];
    const u32 sb = smem_u32(smem);

    const int tid  = threadIdx.x;
    const int wid  = tid >> 5;
    const int lane = tid & 31;
    const int gq   = lane >> 2;
    const int tq   = lane & 3;
    const int wr   = (wid & 1) * 64;
    const int wc   = (wid >> 1) * 32;

    const int bid = blockIdx.x;
    int si = 0;
    #pragma unroll
    for (int i = 1; i < 7; i++)
        if (i < m.nseg && bid >= m.s[i].blk0) si = i;
    const u16* __restrict__ AH  = m.s[si].AH;
    const u16* __restrict__ AL  = m.s[si].AL;
    const u16* __restrict__ A2H = m.s[si].A2H;
    const u16* __restrict__ A2L = m.s[si].A2L;
    const u16* __restrict__ BH  = m.s[si].BH;
    const u16* __restrict__ BL  = m.s[si].BL;
    const float* __restrict__ bias  = m.s[si].bias;
    const float* __restrict__ bias2 = m.s[si].bias2;
    float* __restrict__ C = m.s[si].C;
    u16* __restrict__ CH = m.s[si].CH;
    u16* __restrict__ CL = m.s[si].CL;
    const int M = m.s[si].M, N = m.s[si].N, K = m.s[si].K, Ksp = m.s[si].Ksp;
    const int epi = m.s[si].epi;
    const int local = bid - m.s[si].blk0;
    const int gx = m.s[si].gx;
    const int row0 = (local / gx) * 128;
    const int col0 = (local % gx) * 128;

    float acc[4][4][4];
    #pragma unroll
    for (int i = 0; i < 4; i++)
        #pragma unroll
        for (int j = 0; j < 4; j++)
            #pragma unroll
            for (int q = 0; q < 4; q++) acc[i][j][q] = 0.f;

    auto issue = [&](int s, int buf) {
        const int k0 = s * 32;
        #pragma unroll
        for (int it = 0; it < 2; it++) {
            int c = it * 256 + tid;
            int r = c >> 2, q = c & 3;
            const u32 dst = sb + buf * STAGEB + r * ROWB + q * 16;
            int kk = k0 + q * 8;
            {
                const u16* bh = AH; const u16* bl = AL;
                int ka = kk;
                if (ka >= Ksp) { bh = A2H; bl = A2L; ka -= Ksp; }
                int gr = row0 + r;
                int ok = (gr < M) ? 16 : 0;
                int grc = (gr < M) ? gr : (M - 1);
                cpasync16(dst,          bh + (size_t)grc * Ksp + ka, ok);
                cpasync16(dst + PLANEB, bl + (size_t)grc * Ksp + ka, ok);
            }
            {
                size_t off = (size_t)(col0 + r) * K + kk;
                cpasync16(dst + 2 * PLANEB, BH + off, 16);
                cpasync16(dst + 3 * PLANEB, BL + off, 16);
            }
        }
    };

    const int lr = lane & 7;
    const int lb = (lane >> 3) & 1;
    const int lh = lane >> 4;
    const u32 aoff = (u32)((wr + lb * 8 + lr) * ROWB + lh * 16);
    const u32 boff = (u32)((wc + lh * 8 + lr) * ROWB + lb * 16) + 2 * PLANEB;

    auto compute = [&](int buf) {
        const u32 base = sb + buf * STAGEB;
        #pragma unroll
        for (int kc = 0; kc < 2; kc++) {
            const u32 ka = base + aoff + kc * 32;
            const u32 kb = base + boff + kc * 32;
            u32 ah[4][4], bh[4][2], bl[4][2];
            #pragma unroll
            for (int mi = 0; mi < 4; mi++)
                ldsm4(ah[mi][0], ah[mi][1], ah[mi][2], ah[mi][3],
                      ka + mi * (16 * ROWB));
            #pragma unroll
            for (int nj = 0; nj < 2; nj++)
                ldsm4(bh[2 * nj][0], bh[2 * nj][1], bh[2 * nj + 1][0], bh[2 * nj + 1][1],
                      kb + nj * (16 * ROWB));
            #pragma unroll
            for (int mi = 0; mi < 4; mi++)
                #pragma unroll
                for (int ni = 0; ni < 4; ni++)
                    mma16(acc[mi][ni], ah[mi][0], ah[mi][1], ah[mi][2], ah[mi][3],
                          bh[ni][0], bh[ni][1]);
            #pragma unroll
            for (int nj = 0; nj < 2; nj++)
                ldsm4(bl[2 * nj][0], bl[2 * nj][1], bl[2 * nj + 1][0], bl[2 * nj + 1][1],
                      kb + PLANEB + nj * (16 * ROWB));
            #pragma unroll
            for (int mi = 0; mi < 4; mi++)
                #pragma unroll
                for (int ni = 0; ni < 4; ni++)
                    mma16(acc[mi][ni], ah[mi][0], ah[mi][1], ah[mi][2], ah[mi][3],
                          bl[ni][0], bl[ni][1]);
            #pragma unroll
            for (int mi = 0; mi < 4; mi++)
                ldsm4(ah[mi][0], ah[mi][1], ah[mi][2], ah[mi][3],
                      ka + PLANEB + mi * (16 * ROWB));
            #pragma unroll
            for (int mi = 0; mi < 4; mi++)
                #pragma unroll
                for (int ni = 0; ni < 4; ni++)
                    mma16(acc[mi][ni], ah[mi][0], ah[mi][1], ah[mi][2], ah[mi][3],
                          bh[ni][0], bh[ni][1]);
        }
    };

    const int nst = K / 32;
    issue(0, 0);
    cpcommit();

    for (int s = 0; s < nst; s++) {
        cpwait<0>();
        __syncthreads();
        if (s + 1 < nst) issue(s + 1, (s + 1) & 1);
        cpcommit();
        compute(s & 1);
    }

    #pragma unroll
    for (int mi = 0; mi < 4; mi++) {
        #pragma unroll
        for (int rr = 0; rr < 2; rr++) {
            int r = row0 + wr + mi * 16 + gq + rr * 8;
            if (r >= M) continue;
            float gg = (epi == 4) ? m.gate[r] : 0.f;
            #pragma unroll
            for (int ni = 0; ni < 4; ni++) {
                int c = col0 + wc + ni * 8 + tq * 2;
                float s0 = acc[mi][ni][rr * 2 + 0] + bias[c];
                float s1 = acc[mi][ni][rr * 2 + 1] + bias[c + 1];
                if (epi == 2) {
                    u32 hw = packbf(s0, s1);
                    float l0 = s0 - bf_lo_f(hw);
                    float l1 = s1 - bf_hi_f(hw);
                    size_t pidx = (size_t)r * (N >> 1) + (c >> 1);
                    ((u32*)CH)[pidx] = hw;
                    ((u32*)CL)[pidx] = packbf(l0, l1);
                } else {
                    size_t idx = (size_t)r * N + c;
                    float2 o;
                    if (epi == 0) {
                        o = make_float2(s0, s1);
                    } else if (epi == 1) {
                        o = make_float2(fmaxf(s0, 0.f), fmaxf(s1, 0.f));
                    } else {  // epi 4: s already has bias; redo with dual bias
                        float a0 = acc[mi][ni][rr * 2 + 0];
                        float a1 = acc[mi][ni][rr * 2 + 1];
                        o = make_float2(
                            a0 + gg * bias[c]     + (1.f - gg) * bias2[c],
                            a1 + gg * bias[c + 1] + (1.f - gg) * bias2[c + 1]);
                    }
                    *(float2*)(C + idx) = o;
                }
            }
        }
    }
}

// ---------------- flash attention: MMA QK scores + scalar softmax/PV --------
// Block: 128 threads = 128 query rows; 4 warps each own 32 score rows.
// smem: Qh[128x144] Ql Kh[64x144] Kl Vs(fp32 64x256B) Ss[128x66 f32]
static constexpr int FA_ROWB = 144;
static constexpr int FA_QH = 0;
static constexpr int FA_QL = 128 * FA_ROWB;          // 18432
static constexpr int FA_KH = 2 * 128 * FA_ROWB;      // 36864
static constexpr int FA_KL = FA_KH + 64 * FA_ROWB;   // 46080
static constexpr int FA_VS = FA_KL + 64 * FA_ROWB;   // 55296
static constexpr int FA_SS = FA_VS + 16384;          // 71680
static constexpr int FA_SMEM = FA_SS + 128 * 66 * 4; // 105472

struct FArg {
    const u16* QH[2]; const u16* QL[2];
    const u16* KH[2]; const u16* KL[2];
    const float* Vb[2];
    u32* OH[2]; u32* OL[2];
};

__global__ __launch_bounds__(128)
void flash_attn(FArg f, int S, const float* __restrict__ G)
{
    extern __shared__ __align__(16) char fsm[];
    const u32 sb = smem_u32(fsm);
    float* Ss = (float*)(fsm + FA_SS);
    const u64* Vs = (const u64*)(fsm + FA_VS);

    const int tid  = threadIdx.x;
    const int wid  = tid >> 5;
    const int lane = tid & 31;
    const int gq   = lane >> 2;
    const int tq   = lane & 3;
    const int h    = blockIdx.y;
    const int sel  = blockIdx.z >> 3;
    const int b    = blockIdx.z & 7;
    const int row0 = b * 512 + blockIdx.x * 128;
    const int row  = row0 + tid;

    const u16* __restrict__ QHp = f.QH[sel];
    const u16* __restrict__ QLp = f.QL[sel];
    const u16* __restrict__ KHp = f.KH[sel];
    const u16* __restrict__ KLp = f.KL[sel];
    const float* __restrict__ Vb = f.Vb[sel];

    // Q tile (128 rows x 64 dims, hi+lo) — loaded once
    #pragma unroll
    for (int i = 0; i < 8; i++) {
        int c = i * 128 + tid;
        int r = c >> 3, q8 = c & 7;
        size_t src = (size_t)(row0 + r) * 1024 + h * 64 + q8 * 8;
        cpasync16(sb + FA_QH + r * FA_ROWB + q8 * 16, QHp + src, 16);
        cpasync16(sb + FA_QL + r * FA_ROWB + q8 * 16, QLp + src, 16);
    }
    cpcommit();

    u64 acc2[32] = {};
    float mrun = -1e30f, lsum = 0.f;
    const float scale = 0.125f;

    const int lr = lane & 7;
    const int lb = (lane >> 3) & 1;
    const int lh = lane >> 4;
    const u32 qoff = sb + FA_QH + (u32)((wid * 32 + lb * 8 + lr) * FA_ROWB + lh * 16);
    const u32 koff = sb + FA_KH + (u32)((lh * 8 + lr) * FA_ROWB + lb * 16);

    for (int s0 = 0; s0 < S; s0 += 64) {
        const int jmax = (S - s0 < 64) ? (S - s0) : 64;
        // K tile (64x64 hi+lo)
        #pragma unroll
        for (int i = 0; i < 4; i++) {
            int c = i * 128 + tid;
            int r = c >> 3, q8 = c & 7;
            int srow = s0 + r;
            int ok = (srow < S) ? 16 : 0;
            int sr  = (srow < S) ? srow : (S - 1);
            size_t src = (size_t)sr * 1024 + h * 64 + q8 * 8;
            cpasync16(sb + FA_KH + r * FA_ROWB + q8 * 16, KHp + src, ok);
            cpasync16(sb + FA_KL + r * FA_ROWB + q8 * 16, KLp + src, ok);
        }
        // V tile (64 keys x 64 dims fp32, 256B/row)
        #pragma unroll
        for (int i = 0; i < 8; i++) {
            int c = i * 128 + tid;
            int r = c >> 4, q16 = c & 15;
            int srow = s0 + r;
            int ok = (srow < S) ? 16 : 0;
            int sr  = (srow < S) ? srow : (S - 1);
            cpasync16(sb + FA_VS + r * 256 + q16 * 16,
                      Vb + (size_t)sr * 1024 + h * 64 + q16 * 4, ok);
        }
        cpcommit();
        cpwait<0>();
        __syncthreads();

        // QK scores via 3xBF16 MMA: scores[128 x 64], warp owns 32 rows
        #pragma unroll
        for (int mi = 0; mi < 2; mi++) {
            float cs[8][4];
            #pragma unroll
            for (int ni = 0; ni < 8; ni++)
                #pragma unroll
                for (int q = 0; q < 4; q++) cs[ni][q] = 0.f;
            #pragma unroll
            for (int kk = 0; kk < 4; kk++) {
                u32 ah[4], al[4], bh[8][2], bl[8][2];
                ldsm4(ah[0], ah[1], ah[2], ah[3],
                      qoff + mi * (16 * FA_ROWB) + kk * 32);
                ldsm4(al[0], al[1], al[2], al[3],
                      qoff + (FA_QL - FA_QH) + mi * (16 * FA_ROWB) + kk * 32);
                #pragma unroll
                for (int nj = 0; nj < 4; nj++)
                    ldsm4(bh[2 * nj][0], bh[2 * nj][1],
                          bh[2 * nj + 1][0], bh[2 * nj + 1][1],
                          koff + nj * (16 * FA_ROWB) + kk * 32);
                #pragma unroll
                for (int nj = 0; nj < 4; nj++)
                    ldsm4(bl[2 * nj][0], bl[2 * nj][1],
                          bl[2 * nj + 1][0], bl[2 * nj + 1][1],
                          koff + (FA_KL - FA_KH) + nj * (16 * FA_ROWB) + kk * 32);
                #pragma unroll
                for (int ni = 0; ni < 8; ni++)
                    mma16(cs[ni], ah[0], ah[1], ah[2], ah[3], bh[ni][0], bh[ni][1]);
                #pragma unroll
                for (int ni = 0; ni < 8; ni++)
                    mma16(cs[ni], ah[0], ah[1], ah[2], ah[3], bl[ni][0], bl[ni][1]);
                #pragma unroll
                for (int ni = 0; ni < 8; ni++)
                    mma16(cs[ni], al[0], al[1], al[2], al[3], bh[ni][0], bh[ni][1]);
            }
            int r0 = wid * 32 + mi * 16 + gq;
            #pragma unroll
            for (int ni = 0; ni < 8; ni++) {
                int cc = ni * 8 + tq * 2;
                *(float2*)&Ss[r0 * 66 + cc] =
                    make_float2(cs[ni][0] * scale, cs[ni][1] * scale);
                *(float2*)&Ss[(r0 + 8) * 66 + cc] =
                    make_float2(cs[ni][2] * scale, cs[ni][3] * scale);
            }
        }
        __syncthreads();

        // per-row softmax + scalar PV (thread t = row t)
        const float* sp = &Ss[tid * 66];
        float tmax = -1e30f;
        #pragma unroll 8
        for (int j = 0; j < jmax; j++) tmax = fmaxf(tmax, sp[j]);

        float mnew  = fmaxf(mrun, tmax);
        float alpha = __expf(mrun - mnew);
        lsum *= alpha;
        u64 a2 = pack2(alpha, alpha);
        #pragma unroll
        for (int e = 0; e < 32; e++) acc2[e] = mul2(acc2[e], a2);

        #pragma unroll 4
        for (int j = 0; j < jmax; j++) {
            float p = __expf(sp[j] - mnew);
            lsum += p;
            u64 p2 = pack2(p, p);
            const ulonglong2* vp = (const ulonglong2*)&Vs[j * 32];
            #pragma unroll
            for (int e = 0; e < 16; e++) {
                ulonglong2 vv = vp[e];
                fma2(acc2[e * 2],     p2, vv.x);
                fma2(acc2[e * 2 + 1], p2, vv.y);
            }
        }
        mrun = mnew;
        __syncthreads();
    }

    float gv = G[row];
    float gs = (sel == 0) ? gv : (1.f - gv);
    float inv = gs / lsum;
    u32* OH = f.OH[sel];
    u32* OL = f.OL[sel];
    size_t obase = (size_t)row * 512 + h * 32;
    #pragma unroll
    for (int e = 0; e < 32; e++) {
        float2 v = unpack2(acc2[e]);
        v.x *= inv; v.y *= inv;
        u32 hw = packbf(v.x, v.y);
        float l0 = v.x - bf_lo_f(hw);
        float l1 = v.y - bf_hi_f(hw);
        OH[obase + e] = hw;
        OL[obase + e] = packbf(l0, l1);
    }
}

// ---------------- gate: G[r] = sigmoid(H[r,:] . W2 + b2), one warp per row ----
__global__ __launch_bounds__(256)
void gate_kernel(const float* __restrict__ H, const float* __restrict__ W2,
                 const float* __restrict__ b2, float* __restrict__ G)
{
    int w = (blockIdx.x * blockDim.x + threadIdx.x) >> 5;
    int lane = threadIdx.x & 31;
    const float* hp = H + (size_t)w * 1024;
    float s = 0.f;
    #pragma unroll
    for (int i = 0; i < 32; i++) s += hp[lane + i * 32] * W2[lane + i * 32];
    #pragma unroll
    for (int o = 16; o; o >>= 1) s += __shfl_xor_sync(0xffffffffu, s, o);
    if (lane == 0) G[w] = 1.f / (1.f + __expf(-(s + b2[0])));
}

// ---------------- launch ----------------
extern "C" void kernel_launch(void* const* d_in, const int* in_sizes, int n_in,
                              void* d_out, int out_size)
{
    const float* trend  = (const float*)d_in[0];
    const float* detail = (const float*)d_in[1];
    const float* protoT = (const float*)d_in[2];
    const float* protoD = (const float*)d_in[3];
    const float* tWq = (const float*)d_in[4];  const float* tbq = (const float*)d_in[5];
    const float* tWk = (const float*)d_in[6];  const float* tbk = (const float*)d_in[7];
    const float* tWv = (const float*)d_in[8];  const float* tbv = (const float*)d_in[9];
    const float* tWo = (const float*)d_in[10]; const float* tbo = (const float*)d_in[11];
    const float* dWq = (const float*)d_in[12]; const float* dbq = (const float*)d_in[13];
    const float* dWk = (const float*)d_in[14]; const float* dbk = (const float*)d_in[15];
    const float* dWv = (const float*)d_in[16]; const float* dbv = (const float*)d_in[17];
    const float* dWo = (const float*)d_in[18]; const float* dbo = (const float*)d_in[19];
    const float* gW1 = (const float*)d_in[20]; const float* gb1 = (const float*)d_in[21];
    const float* gW2 = (const float*)d_in[22]; const float* gb2 = (const float*)d_in[23];
    float* out = (float*)d_out;

    #define SYM(T, v, s) T* v; cudaGetSymbolAddress((void**)&v, s)
    SYM(float, Vt, g_Vt);   SYM(float, Vd, g_Vd);
    SYM(float, H,  g_H);    SYM(float, G,  g_gate);
    SYM(u16, QtH, g_QtH);   SYM(u16, QtL, g_QtL);
    SYM(u16, QdH, g_QdH);   SYM(u16, QdL, g_QdL);
    SYM(u16, KtH, g_KtH);   SYM(u16, KtL, g_KtL);
    SYM(u16, KdH, g_KdH);   SYM(u16, KdL, g_KdL);
    SYM(u16, trH, g_trH);   SYM(u16, trL, g_trL);
    SYM(u16, deH, g_deH);   SYM(u16, deL, g_deL);
    SYM(u16, pTH, g_pTH);   SYM(u16, pTL, g_pTL);
    SYM(u16, pDH, g_pDH);   SYM(u16, pDL, g_pDL);
    SYM(u16, ctH, g_ctH);   SYM(u16, ctL, g_ctL);
    SYM(u16, cdH, g_cdH);   SYM(u16, cdL, g_cdL);
    SYM(u16, wqtH, g_wqtH); SYM(u16, wqtL, g_wqtL);
    SYM(u16, wqdH, g_wqdH); SYM(u16, wqdL, g_wqdL);
    SYM(u16, wktH, g_wktH); SYM(u16, wktL, g_wktL);
    SYM(u16, wvtH, g_wvtH); SYM(u16, wvtL, g_wvtL);
    SYM(u16, wkdH, g_wkdH); SYM(u16, wkdL, g_wkdL);
    SYM(u16, wvdH, g_wvdH); SYM(u16, wvdL, g_wvdL);
    SYM(u16, woH, g_woH);   SYM(u16, woL, g_woL);
    SYM(u16, gw1H, g_gw1H); SYM(u16, gw1L, g_gw1L);
    #undef SYM

    cudaFuncSetAttribute(tgemm, cudaFuncAttributeMaxDynamicSharedMemorySize, SMEM_DYN);
    cudaFuncSetAttribute(flash_attn, cudaFuncAttributeMaxDynamicSharedMemorySize, FA_SMEM);

    // 0a) A-side conversions
    {
        CArg c = {};
        c.src[0] = trend;  c.dH[0] = (u32*)trH; c.dL[0] = (u32*)trL; c.n2[0] = 4096 * 512;
        c.src[1] = detail; c.dH[1] = (u32*)deH; c.dL[1] = (u32*)deL; c.n2[1] = 4096 * 512;
        c.src[2] = protoT; c.dH[2] = (u32*)pTH; c.dL[2] = (u32*)pTL; c.n2[2] = 1000 * 2048;
        c.src[3] = protoD; c.dH[3] = (u32*)pDH; c.dL[3] = (u32*)pDL; c.n2[3] = 1000 * 2048;
        convA<<<dim3(8192, 4), 256>>>(c);
    }
    // 0b) weight transpose+split
    {
        TArg t = {};
        int i = 0;
        auto add = [&](const float* s, u16* h, u16* l, int K, int N, int ldk, int koff) {
            t.src[i] = s; t.dH[i] = h; t.dL[i] = l;
            t.K[i] = K; t.N[i] = N; t.ldk[i] = ldk; t.koff[i] = koff; i++;
        };
        add(tWq, wqtH, wqtL, 1024, 1024, 1024, 0);
        add(dWq, wqdH, wqdL, 1024, 1024, 1024, 0);
        add(tWk, wktH, wktL, 4096, 1024, 4096, 0);
        add(tWv, wvtH, wvtL, 4096, 1024, 4096, 0);
        add(dWk, wkdH, wkdL, 4096, 1024, 4096, 0);
        add(dWv, wvdH, wvdL, 4096, 1024, 4096, 0);
        add(tWo, woH,  woL,  1024, 4096, 2048, 0);
        add(dWo, woH,  woL,  1024, 4096, 2048, 1024);
        add(gW1, gw1H, gw1L, 2048, 1024, 2048, 0);
        convB<<<dim3(128, 128, 9), dim3(32, 8)>>>(t);
    }

    // 1) merged pre-attention GEMMs (1024 CTAs)
    {
        MArg a = {};
        int blk = 0, i = 0;
        auto seg = [&](const u16* ah, const u16* al, const u16* a2h, const u16* a2l,
                       const u16* bh, const u16* bl, const float* bi,
                       float* c, u16* ch, u16* cl,
                       int M, int N, int K, int ksp, int epi) {
            Seg& s = a.s[i++];
            s.AH = ah; s.AL = al; s.A2H = a2h; s.A2L = a2l; s.BH = bh; s.BL = bl;
            s.bias = bi; s.bias2 = nullptr; s.C = c; s.CH = ch; s.CL = cl;
            s.M = M; s.N = N; s.K = K; s.Ksp = ksp; s.epi = epi;
            s.gx = N / 128; s.blk0 = blk;
            blk += (N / 128) * ((M + 127) / 128);
        };
        seg(trH, trL, deH, deL, gw1H, gw1L, gb1, H, nullptr, nullptr,
            4096, 1024, 2048, 1024, 1);
        seg(trH, trL, trH, trL, wqtH, wqtL, tbq, nullptr, QtH, QtL,
            4096, 1024, 1024, 1024, 2);
        seg(deH, deL, deH, deL, wqdH, wqdL, dbq, nullptr, QdH, QdL,
            4096, 1024, 1024, 1024, 2);
        seg(pTH, pTL, pTH, pTL, wktH, wktL, tbk, nullptr, KtH, KtL,
            1000, 1024, 4096, 4096, 2);
        seg(pTH, pTL, pTH, pTL, wvtH, wvtL, tbv, Vt, nullptr, nullptr,
            1000, 1024, 4096, 4096, 0);
        seg(pDH, pDL, pDH, pDL, wkdH, wkdL, dbk, nullptr, KdH, KdL,
            1000, 1024, 4096, 4096, 2);
        seg(pDH, pDL, pDH, pDL, wvdH, wvdL, dbv, Vd, nullptr, nullptr,
            1000, 1024, 4096, 4096, 0);
        a.nseg = i;
        a.gate = G;
        tgemm<<<blk, 256, SMEM_DYN>>>(a);
    }
    // 2) gate
    gate_kernel<<<512, 256>>>(H, gW2, gb2, G);

    // 3) attention (MMA QK + scalar PV; gate-scaled bf16 hi/lo output)
    {
        FArg fa = {};
        fa.QH[0] = QtH; fa.QL[0] = QtL; fa.KH[0] = KtH; fa.KL[0] = KtL;
        fa.Vb[0] = Vt;  fa.OH[0] = (u32*)ctH; fa.OL[0] = (u32*)ctL;
        fa.QH[1] = QdH; fa.QL[1] = QdL; fa.KH[1] = KdH; fa.KL[1] = KdL;
        fa.Vb[1] = Vd;  fa.OH[1] = (u32*)cdH; fa.OL[1] = (u32*)cdL;
        flash_attn<<<dim3(4, 16, 16), 128, FA_SMEM>>>(fa, 1000, G);
    }
    // 4) merged output projection + blend (single segment, epi 4)
    {
        MArg a = {};
        Seg& s = a.s[0];
        s.AH = ctH; s.AL = ctL; s.A2H = cdH; s.A2L = cdL;
        s.BH = woH; s.BL = woL;
        s.bias = tbo; s.bias2 = dbo; s.C = out; s.CH = nullptr; s.CL = nullptr;
        s.M = 4096; s.N = 4096; s.K = 2048; s.Ksp = 1024; s.epi = 4;
        s.gx = 32; s.blk0 = 0;
        a.nseg = 1;
        a.gate = G;
        tgemm<<<1024, 256, SMEM_DYN>>>(a);
    }

    (void)in_sizes; (void)n_in; (void)out_size;
}

// round 16
// speedup vs baseline: 1.6624x; 1.2951x over previous
#include <cuda_runtime.h>
#include <cuda_bf16.h>
#include <cstdint>

typedef unsigned long long u64;
typedef unsigned int u32;
typedef unsigned short u16;

// ---------------- bf16 helpers ----------------
__device__ __forceinline__ u32 packbf(float v0, float v1) {
    u32 r; asm("cvt.rn.bf16x2.f32 %0, %1, %2;" : "=r"(r) : "f"(v1), "f"(v0));
    return r;
}
__device__ __forceinline__ float bf_lo_f(u32 w) { return __uint_as_float(w << 16); }
__device__ __forceinline__ float bf_hi_f(u32 w) { return __uint_as_float(w & 0xffff0000u); }

// m16n8k16 bf16 MMA, row.col, fp32 accumulate
__device__ __forceinline__ void mma16(float* c, u32 a0, u32 a1, u32 a2, u32 a3,
                                      u32 b0, u32 b1) {
    asm volatile("mma.sync.aligned.m16n8k16.row.col.f32.bf16.bf16.f32 "
                 "{%0,%1,%2,%3}, {%4,%5,%6,%7}, {%8,%9}, {%0,%1,%2,%3};"
                 : "+f"(c[0]), "+f"(c[1]), "+f"(c[2]), "+f"(c[3])
                 : "r"(a0), "r"(a1), "r"(a2), "r"(a3), "r"(b0), "r"(b1));
}

// ---------------- cp.async / ldmatrix ----------------
__device__ __forceinline__ u32 smem_u32(const void* p) {
    u32 a; asm("{ .reg .u64 t; cvta.to.shared.u64 t, %1; cvt.u32.u64 %0, t; }"
                : "=r"(a) : "l"(p));
    return a;
}
__device__ __forceinline__ void cpasync16(u32 dst, const void* src, int srcsize) {
    asm volatile("cp.async.cg.shared.global [%0], [%1], 16, %2;"
                 :: "r"(dst), "l"(src), "r"(srcsize) : "memory");
}
__device__ __forceinline__ void cpcommit() {
    asm volatile("cp.async.commit_group;" ::: "memory");
}
template<int N> __device__ __forceinline__ void cpwait() {
    asm volatile("cp.async.wait_group %0;" :: "n"(N) : "memory");
}
__device__ __forceinline__ void ldsm4(u32& r0, u32& r1, u32& r2, u32& r3, u32 addr) {
    asm volatile("ldmatrix.sync.aligned.m8n8.x4.shared.b16 {%0,%1,%2,%3}, [%4];"
                 : "=r"(r0), "=r"(r1), "=r"(r2), "=r"(r3) : "r"(addr));
}
__device__ __forceinline__ void ldsm4t(u32& r0, u32& r1, u32& r2, u32& r3, u32 addr) {
    asm volatile("ldmatrix.sync.aligned.m8n8.x4.trans.shared.b16 {%0,%1,%2,%3}, [%4];"
                 : "=r"(r0), "=r"(r1), "=r"(r2), "=r"(r3) : "r"(addr));
}

// ---------------- scratch (device globals: allocation-free) ----------------
__device__ float g_H [4096 * 1024];
__device__ float g_gate[4096];
__device__ u16 g_QtH[4096 * 1024], g_QtL[4096 * 1024];
__device__ u16 g_QdH[4096 * 1024], g_QdL[4096 * 1024];
__device__ u16 g_KtH[1024 * 1024], g_KtL[1024 * 1024];
__device__ u16 g_KdH[1024 * 1024], g_KdL[1024 * 1024];
__device__ u16 g_VtH[1024 * 1024], g_VtL[1024 * 1024];
__device__ u16 g_VdH[1024 * 1024], g_VdL[1024 * 1024];
__device__ u16 g_trH[4096 * 1024], g_trL[4096 * 1024];
__device__ u16 g_deH[4096 * 1024], g_deL[4096 * 1024];
__device__ u16 g_pTH[1000 * 4096], g_pTL[1000 * 4096];
__device__ u16 g_pDH[1000 * 4096], g_pDL[1000 * 4096];
__device__ u16 g_ctH[4096 * 1024], g_ctL[4096 * 1024];
__device__ u16 g_cdH[4096 * 1024], g_cdL[4096 * 1024];
__device__ u16 g_wqtH[1024 * 1024], g_wqtL[1024 * 1024];
__device__ u16 g_wqdH[1024 * 1024], g_wqdL[1024 * 1024];
__device__ u16 g_wktH[1024 * 4096], g_wktL[1024 * 4096];
__device__ u16 g_wvtH[1024 * 4096], g_wvtL[1024 * 4096];
__device__ u16 g_wkdH[1024 * 4096], g_wkdL[1024 * 4096];
__device__ u16 g_wvdH[1024 * 4096], g_wvdL[1024 * 4096];
__device__ u16 g_woH[4096 * 2048], g_woL[4096 * 2048];
__device__ u16 g_gw1H[1024 * 2048], g_gw1L[1024 * 2048];

// ---------------- pre-pass: elementwise fp32 -> bf16 hi/lo ----------------
struct CArg { const float* src[4]; u32* dH[4]; u32* dL[4]; int n2[4]; };
__global__ __launch_bounds__(256)
void convA(CArg c)
{
    int z = blockIdx.y;
    int i = blockIdx.x * 256 + threadIdx.x;
    if (i >= c.n2[z]) return;
    float2 v = ((const float2*)c.src[z])[i];
    u32 hw = packbf(v.x, v.y);
    float l0 = v.x - bf_lo_f(hw);
    float l1 = v.y - bf_hi_f(hw);
    c.dH[z][i] = hw;
    c.dL[z][i] = packbf(l0, l1);
}

// ---------------- pre-pass: transpose [K,N] fp32 -> [N, ldk] bf16 hi/lo -----
struct TArg {
    const float* src[9]; u16* dH[9]; u16* dL[9];
    int K[9]; int N[9]; int ldk[9]; int koff[9];
};
__global__ __launch_bounds__(256)
void convB(TArg t)
{
    __shared__ float tile[32][33];
    int z = blockIdx.z;
    int K = t.K[z], N = t.N[z], ldk = t.ldk[z], koff = t.koff[z];
    int k0 = blockIdx.x * 32, n0 = blockIdx.y * 32;
    if (k0 >= K || n0 >= N) return;
    const float* src = t.src[z];
    #pragma unroll
    for (int r = 0; r < 4; r++)
        tile[threadIdx.y + r * 8][threadIdx.x] =
            src[(size_t)(k0 + threadIdx.y + r * 8) * N + n0 + threadIdx.x];
    __syncthreads();
    u16* dH = t.dH[z]; u16* dL = t.dL[z];
    #pragma unroll
    for (int r = 0; r < 4; r++) {
        int n = n0 + threadIdx.y + r * 8;
        int k = k0 + threadIdx.x;
        float v = tile[threadIdx.x][threadIdx.y + r * 8];
        __nv_bfloat16 h = __float2bfloat16(v);
        float hf = __bfloat162float(h);
        __nv_bfloat16 l = __float2bfloat16(v - hf);
        dH[(size_t)n * ldk + koff + k] = *(u16*)&h;
        dL[(size_t)n * ldk + koff + k] = *(u16*)&l;
    }
}

// ---------------- segment-dispatch GEMM argument block ----------------
// epi 0: C(fp32) = AB + bias
// epi 1: C(fp32) = relu(AB + bias)
// epi 2: CH/CL(bf16 hi/lo planes) = AB + bias
// epi 4: C(fp32) = AB + g[r]*bias[c] + (1-g[r])*bias2[c]
struct Seg {
    const u16 *AH, *AL, *A2H, *A2L, *BH, *BL;
    const float *bias, *bias2;
    float* C;
    u16 *CH, *CL;
    int M, N, K, Ksp, epi, gx, blk0;
};
struct MArg { Seg s[7]; int nseg; const float* gate; };

// ---------------- HMMA 3xBF16 GEMM: k32 stages, 2-buffer ring, segments -----
static constexpr int ROWB   = 80;
static constexpr int PLANEB = 128 * ROWB;
static constexpr int STAGEB = 4 * PLANEB;
static constexpr int SMEM_DYN = 2 * STAGEB;      // 81920

__global__ __launch_bounds__(256, 2)
void tgemm(MArg m)
{
    extern __shared__ __align__(16) char smem[];
    const u32 sb = smem_u32(smem);

    const int tid  = threadIdx.x;
    const int wid  = tid >> 5;
    const int lane = tid & 31;
    const int gq   = lane >> 2;
    const int tq   = lane & 3;
    const int wr   = (wid & 1) * 64;
    const int wc   = (wid >> 1) * 32;

    const int bid = blockIdx.x;
    int si = 0;
    #pragma unroll
    for (int i = 1; i < 7; i++)
        if (i < m.nseg && bid >= m.s[i].blk0) si = i;
    const u16* __restrict__ AH  = m.s[si].AH;
    const u16* __restrict__ AL  = m.s[si].AL;
    const u16* __restrict__ A2H = m.s[si].A2H;
    const u16* __restrict__ A2L = m.s[si].A2L;
    const u16* __restrict__ BH  = m.s[si].BH;
    const u16* __restrict__ BL  = m.s[si].BL;
    const float* __restrict__ bias  = m.s[si].bias;
    const float* __restrict__ bias2 = m.s[si].bias2;
    float* __restrict__ C = m.s[si].C;
    u16* __restrict__ CH = m.s[si].CH;
    u16* __restrict__ CL = m.s[si].CL;
    const int M = m.s[si].M, N = m.s[si].N, K = m.s[si].K, Ksp = m.s[si].Ksp;
    const int epi = m.s[si].epi;
    const int local = bid - m.s[si].blk0;
    const int gx = m.s[si].gx;
    const int row0 = (local / gx) * 128;
    const int col0 = (local % gx) * 128;

    float acc[4][4][4];
    #pragma unroll
    for (int i = 0; i < 4; i++)
        #pragma unroll
        for (int j = 0; j < 4; j++)
            #pragma unroll
            for (int q = 0; q < 4; q++) acc[i][j][q] = 0.f;

    auto issue = [&](int s, int buf) {
        const int k0 = s * 32;
        #pragma unroll
        for (int it = 0; it < 2; it++) {
            int c = it * 256 + tid;
            int r = c >> 2, q = c & 3;
            const u32 dst = sb + buf * STAGEB + r * ROWB + q * 16;
            int kk = k0 + q * 8;
            {
                const u16* bh = AH; const u16* bl = AL;
                int ka = kk;
                if (ka >= Ksp) { bh = A2H; bl = A2L; ka -= Ksp; }
                int gr = row0 + r;
                int ok = (gr < M) ? 16 : 0;
                int grc = (gr < M) ? gr : (M - 1);
                cpasync16(dst,          bh + (size_t)grc * Ksp + ka, ok);
                cpasync16(dst + PLANEB, bl + (size_t)grc * Ksp + ka, ok);
            }
            {
                size_t off = (size_t)(col0 + r) * K + kk;
                cpasync16(dst + 2 * PLANEB, BH + off, 16);
                cpasync16(dst + 3 * PLANEB, BL + off, 16);
            }
        }
    };

    const int lr = lane & 7;
    const int lb = (lane >> 3) & 1;
    const int lh = lane >> 4;
    const u32 aoff = (u32)((wr + lb * 8 + lr) * ROWB + lh * 16);
    const u32 boff = (u32)((wc + lh * 8 + lr) * ROWB + lb * 16) + 2 * PLANEB;

    auto compute = [&](int buf) {
        const u32 base = sb + buf * STAGEB;
        #pragma unroll
        for (int kc = 0; kc < 2; kc++) {
            const u32 ka = base + aoff + kc * 32;
            const u32 kb = base + boff + kc * 32;
            u32 ah[4][4], bh[4][2], bl[4][2];
            #pragma unroll
            for (int mi = 0; mi < 4; mi++)
                ldsm4(ah[mi][0], ah[mi][1], ah[mi][2], ah[mi][3],
                      ka + mi * (16 * ROWB));
            #pragma unroll
            for (int nj = 0; nj < 2; nj++)
                ldsm4(bh[2 * nj][0], bh[2 * nj][1], bh[2 * nj + 1][0], bh[2 * nj + 1][1],
                      kb + nj * (16 * ROWB));
            #pragma unroll
            for (int mi = 0; mi < 4; mi++)
                #pragma unroll
                for (int ni = 0; ni < 4; ni++)
                    mma16(acc[mi][ni], ah[mi][0], ah[mi][1], ah[mi][2], ah[mi][3],
                          bh[ni][0], bh[ni][1]);
            #pragma unroll
            for (int nj = 0; nj < 2; nj++)
                ldsm4(bl[2 * nj][0], bl[2 * nj][1], bl[2 * nj + 1][0], bl[2 * nj + 1][1],
                      kb + PLANEB + nj * (16 * ROWB));
            #pragma unroll
            for (int mi = 0; mi < 4; mi++)
                #pragma unroll
                for (int ni = 0; ni < 4; ni++)
                    mma16(acc[mi][ni], ah[mi][0], ah[mi][1], ah[mi][2], ah[mi][3],
                          bl[ni][0], bl[ni][1]);
            #pragma unroll
            for (int mi = 0; mi < 4; mi++)
                ldsm4(ah[mi][0], ah[mi][1], ah[mi][2], ah[mi][3],
                      ka + PLANEB + mi * (16 * ROWB));
            #pragma unroll
            for (int mi = 0; mi < 4; mi++)
                #pragma unroll
                for (int ni = 0; ni < 4; ni++)
                    mma16(acc[mi][ni], ah[mi][0], ah[mi][1], ah[mi][2], ah[mi][3],
                          bh[ni][0], bh[ni][1]);
        }
    };

    const int nst = K / 32;
    issue(0, 0);
    cpcommit();

    for (int s = 0; s < nst; s++) {
        cpwait<0>();
        __syncthreads();
        if (s + 1 < nst) issue(s + 1, (s + 1) & 1);
        cpcommit();
        compute(s & 1);
    }

    #pragma unroll
    for (int mi = 0; mi < 4; mi++) {
        #pragma unroll
        for (int rr = 0; rr < 2; rr++) {
            int r = row0 + wr + mi * 16 + gq + rr * 8;
            if (r >= M) continue;
            float gg = (epi == 4) ? m.gate[r] : 0.f;
            #pragma unroll
            for (int ni = 0; ni < 4; ni++) {
                int c = col0 + wc + ni * 8 + tq * 2;
                float s0 = acc[mi][ni][rr * 2 + 0] + bias[c];
                float s1 = acc[mi][ni][rr * 2 + 1] + bias[c + 1];
                if (epi == 2) {
                    u32 hw = packbf(s0, s1);
                    float l0 = s0 - bf_lo_f(hw);
                    float l1 = s1 - bf_hi_f(hw);
                    size_t pidx = (size_t)r * (N >> 1) + (c >> 1);
                    ((u32*)CH)[pidx] = hw;
                    ((u32*)CL)[pidx] = packbf(l0, l1);
                } else {
                    size_t idx = (size_t)r * N + c;
                    float2 o;
                    if (epi == 0) {
                        o = make_float2(s0, s1);
                    } else if (epi == 1) {
                        o = make_float2(fmaxf(s0, 0.f), fmaxf(s1, 0.f));
                    } else {
                        float a0 = acc[mi][ni][rr * 2 + 0];
                        float a1 = acc[mi][ni][rr * 2 + 1];
                        o = make_float2(
                            a0 + gg * bias[c]     + (1.f - gg) * bias2[c],
                            a1 + gg * bias[c + 1] + (1.f - gg) * bias2[c + 1]);
                    }
                    *(float2*)(C + idx) = o;
                }
            }
        }
    }
}

// ---------------- flash attention: full-MMA (QK + PV), register softmax -----
// Block: 128 threads, 128 query rows; warp w owns rows [w*32, w*32+32).
// smem: Qh/Ql [128x144], Kh/Kl [64x144], Vh/Vl [64x144]
static constexpr int FA_ROWB = 144;
static constexpr int FA_QH = 0;
static constexpr int FA_QL = 128 * FA_ROWB;          // 18432
static constexpr int FA_KH = 2 * 128 * FA_ROWB;      // 36864
static constexpr int FA_KL = FA_KH + 64 * FA_ROWB;   // 46080
static constexpr int FA_VH = FA_KL + 64 * FA_ROWB;   // 55296
static constexpr int FA_VL = FA_VH + 64 * FA_ROWB;   // 64512
static constexpr int FA_SMEM = FA_VL + 64 * FA_ROWB; // 73728

struct FArg {
    const u16* QH[2]; const u16* QL[2];
    const u16* KH[2]; const u16* KL[2];
    const u16* VH[2]; const u16* VL[2];
    u32* OH[2]; u32* OL[2];
};

__global__ __launch_bounds__(128)
void flash_attn(FArg f, int S, const float* __restrict__ G)
{
    extern __shared__ __align__(16) char fsm[];
    const u32 sb = smem_u32(fsm);

    const int tid  = threadIdx.x;
    const int wid  = tid >> 5;
    const int lane = tid & 31;
    const int gq   = lane >> 2;
    const int tq   = lane & 3;
    const int h    = blockIdx.y;
    const int sel  = blockIdx.z >> 3;
    const int b    = blockIdx.z & 7;
    const int row0 = b * 512 + blockIdx.x * 128;

    const u16* __restrict__ QHp = f.QH[sel];
    const u16* __restrict__ QLp = f.QL[sel];
    const u16* __restrict__ KHp = f.KH[sel];
    const u16* __restrict__ KLp = f.KL[sel];
    const u16* __restrict__ VHp = f.VH[sel];
    const u16* __restrict__ VLp = f.VL[sel];

    // Q tile (128 rows x 64 dims, hi+lo) — loaded once
    #pragma unroll
    for (int i = 0; i < 8; i++) {
        int c = i * 128 + tid;
        int r = c >> 3, q8 = c & 7;
        size_t src = (size_t)(row0 + r) * 1024 + h * 64 + q8 * 8;
        cpasync16(sb + FA_QH + r * FA_ROWB + q8 * 16, QHp + src, 16);
        cpasync16(sb + FA_QL + r * FA_ROWB + q8 * 16, QLp + src, 16);
    }
    cpcommit();

    float ob[2][8][4];
    #pragma unroll
    for (int mi = 0; mi < 2; mi++)
        #pragma unroll
        for (int ni = 0; ni < 8; ni++)
            #pragma unroll
            for (int q = 0; q < 4; q++) ob[mi][ni][q] = 0.f;
    float mrun[2][2] = {{-1e30f, -1e30f}, {-1e30f, -1e30f}};
    float lrun[2][2] = {{0.f, 0.f}, {0.f, 0.f}};
    const float scale = 0.125f;

    const int lr = lane & 7;
    const int lb = (lane >> 3) & 1;
    const int lh = lane >> 4;
    const u32 qoff = sb + FA_QH + (u32)((wid * 32 + lb * 8 + lr) * FA_ROWB + lh * 16);
    const u32 koff = sb + FA_KH + (u32)((lh * 8 + lr) * FA_ROWB + lb * 16);
    // V trans addressing: rows = keys, cols = dims
    const u32 voff = sb + FA_VH + (u32)((lb * 8 + lr) * FA_ROWB + lh * 16);

    for (int s0 = 0; s0 < S; s0 += 64) {
        const int jmax = (S - s0 < 64) ? (S - s0) : 64;
        // K and V tiles (64x64 hi+lo); OOB rows zero-filled via srcsize=0
        #pragma unroll
        for (int i = 0; i < 4; i++) {
            int c = i * 128 + tid;
            int r = c >> 3, q8 = c & 7;
            int srow = s0 + r;
            int ok = (srow < S) ? 16 : 0;
            int sr  = (srow < S) ? srow : (S - 1);
            size_t src = (size_t)sr * 1024 + h * 64 + q8 * 8;
            cpasync16(sb + FA_KH + r * FA_ROWB + q8 * 16, KHp + src, ok);
            cpasync16(sb + FA_KL + r * FA_ROWB + q8 * 16, KLp + src, ok);
            cpasync16(sb + FA_VH + r * FA_ROWB + q8 * 16, VHp + src, ok);
            cpasync16(sb + FA_VL + r * FA_ROWB + q8 * 16, VLp + src, ok);
        }
        cpcommit();
        cpwait<0>();
        __syncthreads();

        #pragma unroll
        for (int mi = 0; mi < 2; mi++) {
            // ---- QK scores (3xBF16 MMA), warp rows [wid*32+mi*16, +16) ----
            float cs[8][4];
            #pragma unroll
            for (int ni = 0; ni < 8; ni++)
                #pragma unroll
                for (int q = 0; q < 4; q++) cs[ni][q] = 0.f;
            #pragma unroll
            for (int kk = 0; kk < 4; kk++) {
                u32 ah[4], al[4], bh[8][2], bl[8][2];
                ldsm4(ah[0], ah[1], ah[2], ah[3],
                      qoff + mi * (16 * FA_ROWB) + kk * 32);
                ldsm4(al[0], al[1], al[2], al[3],
                      qoff + (FA_QL - FA_QH) + mi * (16 * FA_ROWB) + kk * 32);
                #pragma unroll
                for (int nj = 0; nj < 4; nj++)
                    ldsm4(bh[2 * nj][0], bh[2 * nj][1],
                          bh[2 * nj + 1][0], bh[2 * nj + 1][1],
                          koff + nj * (16 * FA_ROWB) + kk * 32);
                #pragma unroll
                for (int nj = 0; nj < 4; nj++)
                    ldsm4(bl[2 * nj][0], bl[2 * nj][1],
                          bl[2 * nj + 1][0], bl[2 * nj + 1][1],
                          koff + (FA_KL - FA_KH) + nj * (16 * FA_ROWB) + kk * 32);
                #pragma unroll
                for (int ni = 0; ni < 8; ni++)
                    mma16(cs[ni], ah[0], ah[1], ah[2], ah[3], bh[ni][0], bh[ni][1]);
                #pragma unroll
                for (int ni = 0; ni < 8; ni++)
                    mma16(cs[ni], ah[0], ah[1], ah[2], ah[3], bl[ni][0], bl[ni][1]);
                #pragma unroll
                for (int ni = 0; ni < 8; ni++)
                    mma16(cs[ni], al[0], al[1], al[2], al[3], bh[ni][0], bh[ni][1]);
            }
            #pragma unroll
            for (int ni = 0; ni < 8; ni++)
                #pragma unroll
                for (int q = 0; q < 4; q++) cs[ni][q] *= scale;

            // mask padded keys (only final tile)
            if (jmax < 64) {
                #pragma unroll
                for (int ni = 0; ni < 8; ni++) {
                    int c = 8 * ni + 2 * tq;
                    if (c >= jmax)     { cs[ni][0] = -1e30f; cs[ni][2] = -1e30f; }
                    if (c + 1 >= jmax) { cs[ni][1] = -1e30f; cs[ni][3] = -1e30f; }
                }
            }

            // ---- register softmax (rows gq / gq+8), reduce across tq quad --
            float tmax0 = -1e30f, tmax1 = -1e30f;
            #pragma unroll
            for (int ni = 0; ni < 8; ni++) {
                tmax0 = fmaxf(tmax0, fmaxf(cs[ni][0], cs[ni][1]));
                tmax1 = fmaxf(tmax1, fmaxf(cs[ni][2], cs[ni][3]));
            }
            tmax0 = fmaxf(tmax0, __shfl_xor_sync(0xffffffffu, tmax0, 1));
            tmax0 = fmaxf(tmax0, __shfl_xor_sync(0xffffffffu, tmax0, 2));
            tmax1 = fmaxf(tmax1, __shfl_xor_sync(0xffffffffu, tmax1, 1));
            tmax1 = fmaxf(tmax1, __shfl_xor_sync(0xffffffffu, tmax1, 2));

            float mn0 = fmaxf(mrun[mi][0], tmax0);
            float mn1 = fmaxf(mrun[mi][1], tmax1);
            float al0 = __expf(mrun[mi][0] - mn0);
            float al1 = __expf(mrun[mi][1] - mn1);
            mrun[mi][0] = mn0; mrun[mi][1] = mn1;

            float rs0 = 0.f, rs1 = 0.f;
            #pragma unroll
            for (int ni = 0; ni < 8; ni++) {
                cs[ni][0] = __expf(cs[ni][0] - mn0);
                cs[ni][1] = __expf(cs[ni][1] - mn0);
                cs[ni][2] = __expf(cs[ni][2] - mn1);
                cs[ni][3] = __expf(cs[ni][3] - mn1);
                rs0 += cs[ni][0] + cs[ni][1];
                rs1 += cs[ni][2] + cs[ni][3];
            }
            rs0 += __shfl_xor_sync(0xffffffffu, rs0, 1);
            rs0 += __shfl_xor_sync(0xffffffffu, rs0, 2);
            rs1 += __shfl_xor_sync(0xffffffffu, rs1, 1);
            rs1 += __shfl_xor_sync(0xffffffffu, rs1, 2);
            lrun[mi][0] = lrun[mi][0] * al0 + rs0;
            lrun[mi][1] = lrun[mi][1] * al1 + rs1;

            #pragma unroll
            for (int ni = 0; ni < 8; ni++) {
                ob[mi][ni][0] *= al0; ob[mi][ni][1] *= al0;
                ob[mi][ni][2] *= al1; ob[mi][ni][3] *= al1;
            }

            // ---- PV (3xBF16 MMA); P fragments converted in-register --------
            #pragma unroll
            for (int kk = 0; kk < 4; kk++) {
                // A frags from C frags of QK (k-chunk = keys 16kk..16kk+15)
                u32 ph[4], pl[4];
                ph[0] = packbf(cs[2 * kk][0], cs[2 * kk][1]);
                ph[1] = packbf(cs[2 * kk][2], cs[2 * kk][3]);
                ph[2] = packbf(cs[2 * kk + 1][0], cs[2 * kk + 1][1]);
                ph[3] = packbf(cs[2 * kk + 1][2], cs[2 * kk + 1][3]);
                pl[0] = packbf(cs[2 * kk][0] - bf_lo_f(ph[0]),
                               cs[2 * kk][1] - bf_hi_f(ph[0]));
                pl[1] = packbf(cs[2 * kk][2] - bf_lo_f(ph[1]),
                               cs[2 * kk][3] - bf_hi_f(ph[1]));
                pl[2] = packbf(cs[2 * kk + 1][0] - bf_lo_f(ph[2]),
                               cs[2 * kk + 1][1] - bf_hi_f(ph[2]));
                pl[3] = packbf(cs[2 * kk + 1][2] - bf_lo_f(ph[3]),
                               cs[2 * kk + 1][3] - bf_hi_f(ph[3]));
                #pragma unroll
                for (int njp = 0; njp < 4; njp++) {
                    u32 vh0, vh1, vh2, vh3, vl0, vl1, vl2, vl3;
                    u32 va = voff + kk * (16 * FA_ROWB) + njp * 32;
                    ldsm4t(vh0, vh1, vh2, vh3, va);
                    ldsm4t(vl0, vl1, vl2, vl3, va + (FA_VL - FA_VH));
                    mma16(ob[mi][2 * njp],     ph[0], ph[1], ph[2], ph[3], vh0, vh1);
                    mma16(ob[mi][2 * njp + 1], ph[0], ph[1], ph[2], ph[3], vh2, vh3);
                    mma16(ob[mi][2 * njp],     pl[0], pl[1], pl[2], pl[3], vh0, vh1);
                    mma16(ob[mi][2 * njp + 1], pl[0], pl[1], pl[2], pl[3], vh2, vh3);
                    mma16(ob[mi][2 * njp],     ph[0], ph[1], ph[2], ph[3], vl0, vl1);
                    mma16(ob[mi][2 * njp + 1], ph[0], ph[1], ph[2], ph[3], vl2, vl3);
                }
            }
        }
        __syncthreads();
    }

    // epilogue: gate-scaled bf16 hi/lo planes from O fragments
    u32* OH = f.OH[sel];
    u32* OL = f.OL[sel];
    #pragma unroll
    for (int mi = 0; mi < 2; mi++) {
        #pragma unroll
        for (int rr = 0; rr < 2; rr++) {
            int r = row0 + wid * 32 + mi * 16 + gq + rr * 8;
            float gv = G[r];
            float gs = (sel == 0) ? gv : (1.f - gv);
            float inv = gs / lrun[mi][rr];
            size_t obase = (size_t)r * 512 + h * 32;
            #pragma unroll
            for (int ni = 0; ni < 8; ni++) {
                float v0 = ob[mi][ni][rr * 2 + 0] * inv;
                float v1 = ob[mi][ni][rr * 2 + 1] * inv;
                u32 hw = packbf(v0, v1);
                float l0 = v0 - bf_lo_f(hw);
                float l1 = v1 - bf_hi_f(hw);
                OH[obase + 4 * ni + tq] = hw;
                OL[obase + 4 * ni + tq] = packbf(l0, l1);
            }
        }
    }
}

// ---------------- gate: G[r] = sigmoid(H[r,:] . W2 + b2), one warp per row ----
__global__ __launch_bounds__(256)
void gate_kernel(const float* __restrict__ H, const float* __restrict__ W2,
                 const float* __restrict__ b2, float* __restrict__ G)
{
    int w = (blockIdx.x * blockDim.x + threadIdx.x) >> 5;
    int lane = threadIdx.x & 31;
    const float* hp = H + (size_t)w * 1024;
    float s = 0.f;
    #pragma unroll
    for (int i = 0; i < 32; i++) s += hp[lane + i * 32] * W2[lane + i * 32];
    #pragma unroll
    for (int o = 16; o; o >>= 1) s += __shfl_xor_sync(0xffffffffu, s, o);
    if (lane == 0) G[w] = 1.f / (1.f + __expf(-(s + b2[0])));
}

// ---------------- launch ----------------
extern "C" void kernel_launch(void* const* d_in, const int* in_sizes, int n_in,
                              void* d_out, int out_size)
{
    const float* trend  = (const float*)d_in[0];
    const float* detail = (const float*)d_in[1];
    const float* protoT = (const float*)d_in[2];
    const float* protoD = (const float*)d_in[3];
    const float* tWq = (const float*)d_in[4];  const float* tbq = (const float*)d_in[5];
    const float* tWk = (const float*)d_in[6];  const float* tbk = (const float*)d_in[7];
    const float* tWv = (const float*)d_in[8];  const float* tbv = (const float*)d_in[9];
    const float* tWo = (const float*)d_in[10]; const float* tbo = (const float*)d_in[11];
    const float* dWq = (const float*)d_in[12]; const float* dbq = (const float*)d_in[13];
    const float* dWk = (const float*)d_in[14]; const float* dbk = (const float*)d_in[15];
    const float* dWv = (const float*)d_in[16]; const float* dbv = (const float*)d_in[17];
    const float* dWo = (const float*)d_in[18]; const float* dbo = (const float*)d_in[19];
    const float* gW1 = (const float*)d_in[20]; const float* gb1 = (const float*)d_in[21];
    const float* gW2 = (const float*)d_in[22]; const float* gb2 = (const float*)d_in[23];
    float* out = (float*)d_out;

    #define SYM(T, v, s) T* v; cudaGetSymbolAddress((void**)&v, s)
    SYM(float, H,  g_H);    SYM(float, G,  g_gate);
    SYM(u16, QtH, g_QtH);   SYM(u16, QtL, g_QtL);
    SYM(u16, QdH, g_QdH);   SYM(u16, QdL, g_QdL);
    SYM(u16, KtH, g_KtH);   SYM(u16, KtL, g_KtL);
    SYM(u16, KdH, g_KdH);   SYM(u16, KdL, g_KdL);
    SYM(u16, VtH, g_VtH);   SYM(u16, VtL, g_VtL);
    SYM(u16, VdH, g_VdH);   SYM(u16, VdL, g_VdL);
    SYM(u16, trH, g_trH);   SYM(u16, trL, g_trL);
    SYM(u16, deH, g_deH);   SYM(u16, deL, g_deL);
    SYM(u16, pTH, g_pTH);   SYM(u16, pTL, g_pTL);
    SYM(u16, pDH, g_pDH);   SYM(u16, pDL, g_pDL);
    SYM(u16, ctH, g_ctH);   SYM(u16, ctL, g_ctL);
    SYM(u16, cdH, g_cdH);   SYM(u16, cdL, g_cdL);
    SYM(u16, wqtH, g_wqtH); SYM(u16, wqtL, g_wqtL);
    SYM(u16, wqdH, g_wqdH); SYM(u16, wqdL, g_wqdL);
    SYM(u16, wktH, g_wktH); SYM(u16, wktL, g_wktL);
    SYM(u16, wvtH, g_wvtH); SYM(u16, wvtL, g_wvtL);
    SYM(u16, wkdH, g_wkdH); SYM(u16, wkdL, g_wkdL);
    SYM(u16, wvdH, g_wvdH); SYM(u16, wvdL, g_wvdL);
    SYM(u16, woH, g_woH);   SYM(u16, woL, g_woL);
    SYM(u16, gw1H, g_gw1H); SYM(u16, gw1L, g_gw1L);
    #undef SYM

    cudaFuncSetAttribute(tgemm, cudaFuncAttributeMaxDynamicSharedMemorySize, SMEM_DYN);
    cudaFuncSetAttribute(flash_attn, cudaFuncAttributeMaxDynamicSharedMemorySize, FA_SMEM);

    // 0a) A-side conversions
    {
        CArg c = {};
        c.src[0] = trend;  c.dH[0] = (u32*)trH; c.dL[0] = (u32*)trL; c.n2[0] = 4096 * 512;
        c.src[1] = detail; c.dH[1] = (u32*)deH; c.dL[1] = (u32*)deL; c.n2[1] = 4096 * 512;
        c.src[2] = protoT; c.dH[2] = (u32*)pTH; c.dL[2] = (u32*)pTL; c.n2[2] = 1000 * 2048;
        c.src[3] = protoD; c.dH[3] = (u32*)pDH; c.dL[3] = (u32*)pDL; c.n2[3] = 1000 * 2048;
        convA<<<dim3(8192, 4), 256>>>(c);
    }
    // 0b) weight transpose+split
    {
        TArg t = {};
        int i = 0;
        auto add = [&](const float* s, u16* h, u16* l, int K, int N, int ldk, int koff) {
            t.src[i] = s; t.dH[i] = h; t.dL[i] = l;
            t.K[i] = K; t.N[i] = N; t.ldk[i] = ldk; t.koff[i] = koff; i++;
        };
        add(tWq, wqtH, wqtL, 1024, 1024, 1024, 0);
        add(dWq, wqdH, wqdL, 1024, 1024, 1024, 0);
        add(tWk, wktH, wktL, 4096, 1024, 4096, 0);
        add(tWv, wvtH, wvtL, 4096, 1024, 4096, 0);
        add(dWk, wkdH, wkdL, 4096, 1024, 4096, 0);
        add(dWv, wvdH, wvdL, 4096, 1024, 4096, 0);
        add(tWo, woH,  woL,  1024, 4096, 2048, 0);
        add(dWo, woH,  woL,  1024, 4096, 2048, 1024);
        add(gW1, gw1H, gw1L, 2048, 1024, 2048, 0);
        convB<<<dim3(128, 128, 9), dim3(32, 8)>>>(t);
    }

    // 1) merged pre-attention GEMMs (1024 CTAs)
    {
        MArg a = {};
        int blk = 0, i = 0;
        auto seg = [&](const u16* ah, const u16* al, const u16* a2h, const u16* a2l,
                       const u16* bh, const u16* bl, const float* bi,
                       float* c, u16* ch, u16* cl,
                       int M, int N, int K, int ksp, int epi) {
            Seg& s = a.s[i++];
            s.AH = ah; s.AL = al; s.A2H = a2h; s.A2L = a2l; s.BH = bh; s.BL = bl;
            s.bias = bi; s.bias2 = nullptr; s.C = c; s.CH = ch; s.CL = cl;
            s.M = M; s.N = N; s.K = K; s.Ksp = ksp; s.epi = epi;
            s.gx = N / 128; s.blk0 = blk;
            blk += (N / 128) * ((M + 127) / 128);
        };
        seg(trH, trL, deH, deL, gw1H, gw1L, gb1, H, nullptr, nullptr,
            4096, 1024, 2048, 1024, 1);
        seg(trH, trL, trH, trL, wqtH, wqtL, tbq, nullptr, QtH, QtL,
            4096, 1024, 1024, 1024, 2);
        seg(deH, deL, deH, deL, wqdH, wqdL, dbq, nullptr, QdH, QdL,
            4096, 1024, 1024, 1024, 2);
        seg(pTH, pTL, pTH, pTL, wktH, wktL, tbk, nullptr, KtH, KtL,
            1000, 1024, 4096, 4096, 2);
        seg(pTH, pTL, pTH, pTL, wvtH, wvtL, tbv, nullptr, VtH, VtL,
            1000, 1024, 4096, 4096, 2);
        seg(pDH, pDL, pDH, pDL, wkdH, wkdL, dbk, nullptr, KdH, KdL,
            1000, 1024, 4096, 4096, 2);
        seg(pDH, pDL, pDH, pDL, wvdH, wvdL, dbv, nullptr, VdH, VdL,
            1000, 1024, 4096, 4096, 2);
        a.nseg = i;
        a.gate = G;
        tgemm<<<blk, 256, SMEM_DYN>>>(a);
    }
    // 2) gate
    gate_kernel<<<512, 256>>>(H, gW2, gb2, G);

    // 3) attention (full-MMA; gate-scaled bf16 hi/lo output)
    {
        FArg fa = {};
        fa.QH[0] = QtH; fa.QL[0] = QtL; fa.KH[0] = KtH; fa.KL[0] = KtL;
        fa.VH[0] = VtH; fa.VL[0] = VtL;
        fa.OH[0] = (u32*)ctH; fa.OL[0] = (u32*)ctL;
        fa.QH[1] = QdH; fa.QL[1] = QdL; fa.KH[1] = KdH; fa.KL[1] = KdL;
        fa.VH[1] = VdH; fa.VL[1] = VdL;
        fa.OH[1] = (u32*)cdH; fa.OL[1] = (u32*)cdL;
        flash_attn<<<dim3(4, 16, 16), 128, FA_SMEM>>>(fa, 1000, G);
    }
    // 4) merged output projection + blend (single segment, epi 4)
    {
        MArg a = {};
        Seg& s = a.s[0];
        s.AH = ctH; s.AL = ctL; s.A2H = cdH; s.A2L = cdL;
        s.BH = woH; s.BL = woL;
        s.bias = tbo; s.bias2 = dbo; s.C = out; s.CH = nullptr; s.CL = nullptr;
        s.M = 4096; s.N = 4096; s.K = 2048; s.Ksp = 1024; s.epi = 4;
        s.gx = 32; s.blk0 = 0;
        a.nseg = 1;
        a.gate = G;
        tgemm<<<1024, 256, SMEM_DYN>>>(a);
    }

    (void)in_sizes; (void)n_in; (void)out_size;
}

// round 17
// speedup vs baseline: 1.8389x; 1.1062x over previous
#include <cuda_runtime.h>
#include <cuda_bf16.h>
#include <cuda_fp16.h>
#include <cstdint>

typedef unsigned long long u64;
typedef unsigned int u32;
typedef unsigned short u16;

// ---------------- bf16 helpers ----------------
__device__ __forceinline__ u32 packbf(float v0, float v1) {
    u32 r; asm("cvt.rn.bf16x2.f32 %0, %1, %2;" : "=r"(r) : "f"(v1), "f"(v0));
    return r;
}
__device__ __forceinline__ float bf_lo_f(u32 w) { return __uint_as_float(w << 16); }
__device__ __forceinline__ float bf_hi_f(u32 w) { return __uint_as_float(w & 0xffff0000u); }

// m16n8k16 bf16 MMA, row.col, fp32 accumulate
__device__ __forceinline__ void mma16(float* c, u32 a0, u32 a1, u32 a2, u32 a3,
                                      u32 b0, u32 b1) {
    asm volatile("mma.sync.aligned.m16n8k16.row.col.f32.bf16.bf16.f32 "
                 "{%0,%1,%2,%3}, {%4,%5,%6,%7}, {%8,%9}, {%0,%1,%2,%3};"
                 : "+f"(c[0]), "+f"(c[1]), "+f"(c[2]), "+f"(c[3])
                 : "r"(a0), "r"(a1), "r"(a2), "r"(a3), "r"(b0), "r"(b1));
}
// m16n8k16 fp16 MMA, row.col, fp32 accumulate
__device__ __forceinline__ void mma16h(float* c, u32 a0, u32 a1, u32 a2, u32 a3,
                                       u32 b0, u32 b1) {
    asm volatile("mma.sync.aligned.m16n8k16.row.col.f32.f16.f16.f32 "
                 "{%0,%1,%2,%3}, {%4,%5,%6,%7}, {%8,%9}, {%0,%1,%2,%3};"
                 : "+f"(c[0]), "+f"(c[1]), "+f"(c[2]), "+f"(c[3])
                 : "r"(a0), "r"(a1), "r"(a2), "r"(a3), "r"(b0), "r"(b1));
}

// ---------------- cp.async / ldmatrix ----------------
__device__ __forceinline__ u32 smem_u32(const void* p) {
    u32 a; asm("{ .reg .u64 t; cvta.to.shared.u64 t, %1; cvt.u32.u64 %0, t; }"
                : "=r"(a) : "l"(p));
    return a;
}
__device__ __forceinline__ void cpasync16(u32 dst, const void* src, int srcsize) {
    asm volatile("cp.async.cg.shared.global [%0], [%1], 16, %2;"
                 :: "r"(dst), "l"(src), "r"(srcsize) : "memory");
}
__device__ __forceinline__ void cpcommit() {
    asm volatile("cp.async.commit_group;" ::: "memory");
}
template<int N> __device__ __forceinline__ void cpwait() {
    asm volatile("cp.async.wait_group %0;" :: "n"(N) : "memory");
}
__device__ __forceinline__ void ldsm4(u32& r0, u32& r1, u32& r2, u32& r3, u32 addr) {
    asm volatile("ldmatrix.sync.aligned.m8n8.x4.shared.b16 {%0,%1,%2,%3}, [%4];"
                 : "=r"(r0), "=r"(r1), "=r"(r2), "=r"(r3) : "r"(addr));
}
__device__ __forceinline__ void ldsm4t(u32& r0, u32& r1, u32& r2, u32& r3, u32 addr) {
    asm volatile("ldmatrix.sync.aligned.m8n8.x4.trans.shared.b16 {%0,%1,%2,%3}, [%4];"
                 : "=r"(r0), "=r"(r1), "=r"(r2), "=r"(r3) : "r"(addr));
}

// ---------------- scratch (device globals: allocation-free) ----------------
__device__ float g_H [4096 * 1024];
__device__ float g_gate[4096];
__device__ u16 g_QtH[4096 * 1024], g_QtL[4096 * 1024];
__device__ u16 g_QdH[4096 * 1024], g_QdL[4096 * 1024];
__device__ u16 g_KtH[1024 * 1024], g_KtL[1024 * 1024];
__device__ u16 g_KdH[1024 * 1024], g_KdL[1024 * 1024];
__device__ u16 g_VtH[1024 * 1024], g_VtL[1024 * 1024];
__device__ u16 g_VdH[1024 * 1024], g_VdL[1024 * 1024];
__device__ u16 g_trH[4096 * 1024], g_trL[4096 * 1024];
__device__ u16 g_deH[4096 * 1024], g_deL[4096 * 1024];
__device__ u16 g_pTH[1000 * 4096], g_pTL[1000 * 4096];
__device__ u16 g_pDH[1000 * 4096], g_pDL[1000 * 4096];
__device__ u16 g_ctH[4096 * 1024], g_ctL[4096 * 1024];   // fp16 hi/lo (gate-scaled)
__device__ u16 g_cdH[4096 * 1024], g_cdL[4096 * 1024];   // fp16 hi/lo
__device__ u16 g_wqtH[1024 * 1024], g_wqtL[1024 * 1024];
__device__ u16 g_wqdH[1024 * 1024], g_wqdL[1024 * 1024];
__device__ u16 g_wktH[1024 * 4096], g_wktL[1024 * 4096];
__device__ u16 g_wvtH[1024 * 4096], g_wvtL[1024 * 4096];
__device__ u16 g_wkdH[1024 * 4096], g_wkdL[1024 * 4096];
__device__ u16 g_wvdH[1024 * 4096], g_wvdL[1024 * 4096];
__device__ u16 g_woH[4096 * 2048];                        // fp16 single plane
__device__ u16 g_gw1H[1024 * 2048], g_gw1L[1024 * 2048];

// ---------------- pre-pass: elementwise fp32 -> bf16 hi/lo ----------------
struct CArg { const float* src[4]; u32* dH[4]; u32* dL[4]; int n2[4]; };
__global__ __launch_bounds__(256)
void convA(CArg c)
{
    int z = blockIdx.y;
    int i = blockIdx.x * 256 + threadIdx.x;
    if (i >= c.n2[z]) return;
    float2 v = ((const float2*)c.src[z])[i];
    u32 hw = packbf(v.x, v.y);
    float l0 = v.x - bf_lo_f(hw);
    float l1 = v.y - bf_hi_f(hw);
    c.dH[z][i] = hw;
    c.dL[z][i] = packbf(l0, l1);
}

// ---------------- pre-pass: transpose [K,N] fp32 -> [N, ldk] hi/lo ---------
// f16 flag: write single fp16 plane into dH (no lo plane)
struct TArg {
    const float* src[9]; u16* dH[9]; u16* dL[9];
    int K[9]; int N[9]; int ldk[9]; int koff[9]; int f16[9];
};
__global__ __launch_bounds__(256)
void convB(TArg t)
{
    __shared__ float tile[32][33];
    int z = blockIdx.z;
    int K = t.K[z], N = t.N[z], ldk = t.ldk[z], koff = t.koff[z], f16 = t.f16[z];
    int k0 = blockIdx.x * 32, n0 = blockIdx.y * 32;
    if (k0 >= K || n0 >= N) return;
    const float* src = t.src[z];
    #pragma unroll
    for (int r = 0; r < 4; r++)
        tile[threadIdx.y + r * 8][threadIdx.x] =
            src[(size_t)(k0 + threadIdx.y + r * 8) * N + n0 + threadIdx.x];
    __syncthreads();
    u16* dH = t.dH[z]; u16* dL = t.dL[z];
    #pragma unroll
    for (int r = 0; r < 4; r++) {
        int n = n0 + threadIdx.y + r * 8;
        int k = k0 + threadIdx.x;
        float v = tile[threadIdx.x][threadIdx.y + r * 8];
        if (f16) {
            __half h = __float2half(v);
            dH[(size_t)n * ldk + koff + k] = *(u16*)&h;
        } else {
            __nv_bfloat16 h = __float2bfloat16(v);
            float hf = __bfloat162float(h);
            __nv_bfloat16 l = __float2bfloat16(v - hf);
            dH[(size_t)n * ldk + koff + k] = *(u16*)&h;
            dL[(size_t)n * ldk + koff + k] = *(u16*)&l;
        }
    }
}

// ---------------- segment-dispatch GEMM argument block ----------------
// fmt 0: bf16 3-term (Ah·Bh + Ah·Bl + Al·Bh)
// fmt 1: fp16 2-term (Ah·Bh + Al·Bh), B single plane
// epi 0: C=AB+bias | 1: relu | 2: bf16 hi/lo planes | 4: dual-bias gate blend
struct Seg {
    const u16 *AH, *AL, *A2H, *A2L, *BH, *BL;
    const float *bias, *bias2;
    float* C;
    u16 *CH, *CL;
    int M, N, K, Ksp, epi, gx, blk0, fmt;
};
struct MArg { Seg s[7]; int nseg; const float* gate; };

// ---------------- HMMA GEMM: k32 stages, 2-buffer ring, segments ------------
static constexpr int ROWB   = 80;
static constexpr int PLANEB = 128 * ROWB;
static constexpr int STAGEB = 4 * PLANEB;
static constexpr int SMEM_DYN = 2 * STAGEB;      // 81920

__global__ __launch_bounds__(256, 2)
void tgemm(MArg m)
{
    extern __shared__ __align__(16) char smem[];
    const u32 sb = smem_u32(smem);

    const int tid  = threadIdx.x;
    const int wid  = tid >> 5;
    const int lane = tid & 31;
    const int gq   = lane >> 2;
    const int tq   = lane & 3;
    const int wr   = (wid & 1) * 64;
    const int wc   = (wid >> 1) * 32;

    const int bid = blockIdx.x;
    int si = 0;
    #pragma unroll
    for (int i = 1; i < 7; i++)
        if (i < m.nseg && bid >= m.s[i].blk0) si = i;
    const u16* __restrict__ AH  = m.s[si].AH;
    const u16* __restrict__ AL  = m.s[si].AL;
    const u16* __restrict__ A2H = m.s[si].A2H;
    const u16* __restrict__ A2L = m.s[si].A2L;
    const u16* __restrict__ BH  = m.s[si].BH;
    const u16* __restrict__ BL  = m.s[si].BL;
    const float* __restrict__ bias  = m.s[si].bias;
    const float* __restrict__ bias2 = m.s[si].bias2;
    float* __restrict__ C = m.s[si].C;
    u16* __restrict__ CH = m.s[si].CH;
    u16* __restrict__ CL = m.s[si].CL;
    const int M = m.s[si].M, N = m.s[si].N, K = m.s[si].K, Ksp = m.s[si].Ksp;
    const int epi = m.s[si].epi;
    const int fmt = m.s[si].fmt;
    const int local = bid - m.s[si].blk0;
    const int gx = m.s[si].gx;
    const int row0 = (local / gx) * 128;
    const int col0 = (local % gx) * 128;

    float acc[4][4][4];
    #pragma unroll
    for (int i = 0; i < 4; i++)
        #pragma unroll
        for (int j = 0; j < 4; j++)
            #pragma unroll
            for (int q = 0; q < 4; q++) acc[i][j][q] = 0.f;

    auto issue = [&](int s, int buf) {
        const int k0 = s * 32;
        #pragma unroll
        for (int it = 0; it < 2; it++) {
            int c = it * 256 + tid;
            int r = c >> 2, q = c & 3;
            const u32 dst = sb + buf * STAGEB + r * ROWB + q * 16;
            int kk = k0 + q * 8;
            {
                const u16* bh = AH; const u16* bl = AL;
                int ka = kk;
                if (ka >= Ksp) { bh = A2H; bl = A2L; ka -= Ksp; }
                int gr = row0 + r;
                int ok = (gr < M) ? 16 : 0;
                int grc = (gr < M) ? gr : (M - 1);
                cpasync16(dst,          bh + (size_t)grc * Ksp + ka, ok);
                cpasync16(dst + PLANEB, bl + (size_t)grc * Ksp + ka, ok);
            }
            {
                size_t off = (size_t)(col0 + r) * K + kk;
                cpasync16(dst + 2 * PLANEB, BH + off, 16);
                if (fmt == 0)
                    cpasync16(dst + 3 * PLANEB, BL + off, 16);
            }
        }
    };

    const int lr = lane & 7;
    const int lb = (lane >> 3) & 1;
    const int lh = lane >> 4;
    const u32 aoff = (u32)((wr + lb * 8 + lr) * ROWB + lh * 16);
    const u32 boff = (u32)((wc + lh * 8 + lr) * ROWB + lb * 16) + 2 * PLANEB;

    auto compute = [&](int buf) {
        const u32 base = sb + buf * STAGEB;
        #pragma unroll
        for (int kc = 0; kc < 2; kc++) {
            const u32 ka = base + aoff + kc * 32;
            const u32 kb = base + boff + kc * 32;
            if (fmt == 0) {
                u32 ah[4][4], bh[4][2], bl[4][2];
                #pragma unroll
                for (int mi = 0; mi < 4; mi++)
                    ldsm4(ah[mi][0], ah[mi][1], ah[mi][2], ah[mi][3],
                          ka + mi * (16 * ROWB));
                #pragma unroll
                for (int nj = 0; nj < 2; nj++)
                    ldsm4(bh[2 * nj][0], bh[2 * nj][1], bh[2 * nj + 1][0], bh[2 * nj + 1][1],
                          kb + nj * (16 * ROWB));
                #pragma unroll
                for (int mi = 0; mi < 4; mi++)
                    #pragma unroll
                    for (int ni = 0; ni < 4; ni++)
                        mma16(acc[mi][ni], ah[mi][0], ah[mi][1], ah[mi][2], ah[mi][3],
                              bh[ni][0], bh[ni][1]);
                #pragma unroll
                for (int nj = 0; nj < 2; nj++)
                    ldsm4(bl[2 * nj][0], bl[2 * nj][1], bl[2 * nj + 1][0], bl[2 * nj + 1][1],
                          kb + PLANEB + nj * (16 * ROWB));
                #pragma unroll
                for (int mi = 0; mi < 4; mi++)
                    #pragma unroll
                    for (int ni = 0; ni < 4; ni++)
                        mma16(acc[mi][ni], ah[mi][0], ah[mi][1], ah[mi][2], ah[mi][3],
                              bl[ni][0], bl[ni][1]);
                #pragma unroll
                for (int mi = 0; mi < 4; mi++)
                    ldsm4(ah[mi][0], ah[mi][1], ah[mi][2], ah[mi][3],
                          ka + PLANEB + mi * (16 * ROWB));
                #pragma unroll
                for (int mi = 0; mi < 4; mi++)
                    #pragma unroll
                    for (int ni = 0; ni < 4; ni++)
                        mma16(acc[mi][ni], ah[mi][0], ah[mi][1], ah[mi][2], ah[mi][3],
                              bh[ni][0], bh[ni][1]);
            } else {
                // fp16 2-term: (Ah + Al) x Bh
                u32 ah[4][4], bh[4][2];
                #pragma unroll
                for (int mi = 0; mi < 4; mi++)
                    ldsm4(ah[mi][0], ah[mi][1], ah[mi][2], ah[mi][3],
                          ka + mi * (16 * ROWB));
                #pragma unroll
                for (int nj = 0; nj < 2; nj++)
                    ldsm4(bh[2 * nj][0], bh[2 * nj][1], bh[2 * nj + 1][0], bh[2 * nj + 1][1],
                          kb + nj * (16 * ROWB));
                #pragma unroll
                for (int mi = 0; mi < 4; mi++)
                    #pragma unroll
                    for (int ni = 0; ni < 4; ni++)
                        mma16h(acc[mi][ni], ah[mi][0], ah[mi][1], ah[mi][2], ah[mi][3],
                               bh[ni][0], bh[ni][1]);
                #pragma unroll
                for (int mi = 0; mi < 4; mi++)      // reuse ah regs for Al
                    ldsm4(ah[mi][0], ah[mi][1], ah[mi][2], ah[mi][3],
                          ka + PLANEB + mi * (16 * ROWB));
                #pragma unroll
                for (int mi = 0; mi < 4; mi++)
                    #pragma unroll
                    for (int ni = 0; ni < 4; ni++)
                        mma16h(acc[mi][ni], ah[mi][0], ah[mi][1], ah[mi][2], ah[mi][3],
                               bh[ni][0], bh[ni][1]);
            }
        }
    };

    const int nst = K / 32;
    issue(0, 0);
    cpcommit();

    for (int s = 0; s < nst; s++) {
        cpwait<0>();
        __syncthreads();
        if (s + 1 < nst) issue(s + 1, (s + 1) & 1);
        cpcommit();
        compute(s & 1);
    }

    #pragma unroll
    for (int mi = 0; mi < 4; mi++) {
        #pragma unroll
        for (int rr = 0; rr < 2; rr++) {
            int r = row0 + wr + mi * 16 + gq + rr * 8;
            if (r >= M) continue;
            float gg = (epi == 4) ? m.gate[r] : 0.f;
            #pragma unroll
            for (int ni = 0; ni < 4; ni++) {
                int c = col0 + wc + ni * 8 + tq * 2;
                float s0 = acc[mi][ni][rr * 2 + 0] + bias[c];
                float s1 = acc[mi][ni][rr * 2 + 1] + bias[c + 1];
                if (epi == 2) {
                    u32 hw = packbf(s0, s1);
                    float l0 = s0 - bf_lo_f(hw);
                    float l1 = s1 - bf_hi_f(hw);
                    size_t pidx = (size_t)r * (N >> 1) + (c >> 1);
                    ((u32*)CH)[pidx] = hw;
                    ((u32*)CL)[pidx] = packbf(l0, l1);
                } else {
                    size_t idx = (size_t)r * N + c;
                    float2 o;
                    if (epi == 0) {
                        o = make_float2(s0, s1);
                    } else if (epi == 1) {
                        o = make_float2(fmaxf(s0, 0.f), fmaxf(s1, 0.f));
                    } else {
                        float a0 = acc[mi][ni][rr * 2 + 0];
                        float a1 = acc[mi][ni][rr * 2 + 1];
                        o = make_float2(
                            a0 + gg * bias[c]     + (1.f - gg) * bias2[c],
                            a1 + gg * bias[c + 1] + (1.f - gg) * bias2[c + 1]);
                    }
                    *(float2*)(C + idx) = o;
                }
            }
        }
    }
}

// ---------------- flash attention: full-MMA (QK + PV), register softmax -----
static constexpr int FA_ROWB = 144;
static constexpr int FA_QH = 0;
static constexpr int FA_QL = 128 * FA_ROWB;
static constexpr int FA_KH = 2 * 128 * FA_ROWB;
static constexpr int FA_KL = FA_KH + 64 * FA_ROWB;
static constexpr int FA_VH = FA_KL + 64 * FA_ROWB;
static constexpr int FA_VL = FA_VH + 64 * FA_ROWB;
static constexpr int FA_SMEM = FA_VL + 64 * FA_ROWB;

struct FArg {
    const u16* QH[2]; const u16* QL[2];
    const u16* KH[2]; const u16* KL[2];
    const u16* VH[2]; const u16* VL[2];
    u32* OH[2]; u32* OL[2];
};

__global__ __launch_bounds__(128)
void flash_attn(FArg f, int S, const float* __restrict__ G)
{
    extern __shared__ __align__(16) char fsm[];
    const u32 sb = smem_u32(fsm);

    const int tid  = threadIdx.x;
    const int wid  = tid >> 5;
    const int lane = tid & 31;
    const int gq   = lane >> 2;
    const int tq   = lane & 3;
    const int h    = blockIdx.y;
    const int sel  = blockIdx.z >> 3;
    const int b    = blockIdx.z & 7;
    const int row0 = b * 512 + blockIdx.x * 128;

    const u16* __restrict__ QHp = f.QH[sel];
    const u16* __restrict__ QLp = f.QL[sel];
    const u16* __restrict__ KHp = f.KH[sel];
    const u16* __restrict__ KLp = f.KL[sel];
    const u16* __restrict__ VHp = f.VH[sel];
    const u16* __restrict__ VLp = f.VL[sel];

    #pragma unroll
    for (int i = 0; i < 8; i++) {
        int c = i * 128 + tid;
        int r = c >> 3, q8 = c & 7;
        size_t src = (size_t)(row0 + r) * 1024 + h * 64 + q8 * 8;
        cpasync16(sb + FA_QH + r * FA_ROWB + q8 * 16, QHp + src, 16);
        cpasync16(sb + FA_QL + r * FA_ROWB + q8 * 16, QLp + src, 16);
    }
    cpcommit();

    float ob[2][8][4];
    #pragma unroll
    for (int mi = 0; mi < 2; mi++)
        #pragma unroll
        for (int ni = 0; ni < 8; ni++)
            #pragma unroll
            for (int q = 0; q < 4; q++) ob[mi][ni][q] = 0.f;
    float mrun[2][2] = {{-1e30f, -1e30f}, {-1e30f, -1e30f}};
    float lrun[2][2] = {{0.f, 0.f}, {0.f, 0.f}};
    const float scale = 0.125f;

    const int lr = lane & 7;
    const int lb = (lane >> 3) & 1;
    const int lh = lane >> 4;
    const u32 qoff = sb + FA_QH + (u32)((wid * 32 + lb * 8 + lr) * FA_ROWB + lh * 16);
    const u32 koff = sb + FA_KH + (u32)((lh * 8 + lr) * FA_ROWB + lb * 16);
    const u32 voff = sb + FA_VH + (u32)((lb * 8 + lr) * FA_ROWB + lh * 16);

    for (int s0 = 0; s0 < S; s0 += 64) {
        const int jmax = (S - s0 < 64) ? (S - s0) : 64;
        #pragma unroll
        for (int i = 0; i < 4; i++) {
            int c = i * 128 + tid;
            int r = c >> 3, q8 = c & 7;
            int srow = s0 + r;
            int ok = (srow < S) ? 16 : 0;
            int sr  = (srow < S) ? srow : (S - 1);
            size_t src = (size_t)sr * 1024 + h * 64 + q8 * 8;
            cpasync16(sb + FA_KH + r * FA_ROWB + q8 * 16, KHp + src, ok);
            cpasync16(sb + FA_KL + r * FA_ROWB + q8 * 16, KLp + src, ok);
            cpasync16(sb + FA_VH + r * FA_ROWB + q8 * 16, VHp + src, ok);
            cpasync16(sb + FA_VL + r * FA_ROWB + q8 * 16, VLp + src, ok);
        }
        cpcommit();
        cpwait<0>();
        __syncthreads();

        #pragma unroll
        for (int mi = 0; mi < 2; mi++) {
            float cs[8][4];
            #pragma unroll
            for (int ni = 0; ni < 8; ni++)
                #pragma unroll
                for (int q = 0; q < 4; q++) cs[ni][q] = 0.f;
            #pragma unroll
            for (int kk = 0; kk < 4; kk++) {
                u32 ah[4], al[4], bh[8][2], bl[8][2];
                ldsm4(ah[0], ah[1], ah[2], ah[3],
                      qoff + mi * (16 * FA_ROWB) + kk * 32);
                ldsm4(al[0], al[1], al[2], al[3],
                      qoff + (FA_QL - FA_QH) + mi * (16 * FA_ROWB) + kk * 32);
                #pragma unroll
                for (int nj = 0; nj < 4; nj++)
                    ldsm4(bh[2 * nj][0], bh[2 * nj][1],
                          bh[2 * nj + 1][0], bh[2 * nj + 1][1],
                          koff + nj * (16 * FA_ROWB) + kk * 32);
                #pragma unroll
                for (int nj = 0; nj < 4; nj++)
                    ldsm4(bl[2 * nj][0], bl[2 * nj][1],
                          bl[2 * nj + 1][0], bl[2 * nj + 1][1],
                          koff + (FA_KL - FA_KH) + nj * (16 * FA_ROWB) + kk * 32);
                #pragma unroll
                for (int ni = 0; ni < 8; ni++)
                    mma16(cs[ni], ah[0], ah[1], ah[2], ah[3], bh[ni][0], bh[ni][1]);
                #pragma unroll
                for (int ni = 0; ni < 8; ni++)
                    mma16(cs[ni], ah[0], ah[1], ah[2], ah[3], bl[ni][0], bl[ni][1]);
                #pragma unroll
                for (int ni = 0; ni < 8; ni++)
                    mma16(cs[ni], al[0], al[1], al[2], al[3], bh[ni][0], bh[ni][1]);
            }
            #pragma unroll
            for (int ni = 0; ni < 8; ni++)
                #pragma unroll
                for (int q = 0; q < 4; q++) cs[ni][q] *= scale;

            if (jmax < 64) {
                #pragma unroll
                for (int ni = 0; ni < 8; ni++) {
                    int c = 8 * ni + 2 * tq;
                    if (c >= jmax)     { cs[ni][0] = -1e30f; cs[ni][2] = -1e30f; }
                    if (c + 1 >= jmax) { cs[ni][1] = -1e30f; cs[ni][3] = -1e30f; }
                }
            }

            float tmax0 = -1e30f, tmax1 = -1e30f;
            #pragma unroll
            for (int ni = 0; ni < 8; ni++) {
                tmax0 = fmaxf(tmax0, fmaxf(cs[ni][0], cs[ni][1]));
                tmax1 = fmaxf(tmax1, fmaxf(cs[ni][2], cs[ni][3]));
            }
            tmax0 = fmaxf(tmax0, __shfl_xor_sync(0xffffffffu, tmax0, 1));
            tmax0 = fmaxf(tmax0, __shfl_xor_sync(0xffffffffu, tmax0, 2));
            tmax1 = fmaxf(tmax1, __shfl_xor_sync(0xffffffffu, tmax1, 1));
            tmax1 = fmaxf(tmax1, __shfl_xor_sync(0xffffffffu, tmax1, 2));

            float mn0 = fmaxf(mrun[mi][0], tmax0);
            float mn1 = fmaxf(mrun[mi][1], tmax1);
            float al0 = __expf(mrun[mi][0] - mn0);
            float al1 = __expf(mrun[mi][1] - mn1);
            mrun[mi][0] = mn0; mrun[mi][1] = mn1;

            float rs0 = 0.f, rs1 = 0.f;
            #pragma unroll
            for (int ni = 0; ni < 8; ni++) {
                cs[ni][0] = __expf(cs[ni][0] - mn0);
                cs[ni][1] = __expf(cs[ni][1] - mn0);
                cs[ni][2] = __expf(cs[ni][2] - mn1);
                cs[ni][3] = __expf(cs[ni][3] - mn1);
                rs0 += cs[ni][0] + cs[ni][1];
                rs1 += cs[ni][2] + cs[ni][3];
            }
            rs0 += __shfl_xor_sync(0xffffffffu, rs0, 1);
            rs0 += __shfl_xor_sync(0xffffffffu, rs0, 2);
            rs1 += __shfl_xor_sync(0xffffffffu, rs1, 1);
            rs1 += __shfl_xor_sync(0xffffffffu, rs1, 2);
            lrun[mi][0] = lrun[mi][0] * al0 + rs0;
            lrun[mi][1] = lrun[mi][1] * al1 + rs1;

            #pragma unroll
            for (int ni = 0; ni < 8; ni++) {
                ob[mi][ni][0] *= al0; ob[mi][ni][1] *= al0;
                ob[mi][ni][2] *= al1; ob[mi][ni][3] *= al1;
            }

            #pragma unroll
            for (int kk = 0; kk < 4; kk++) {
                u32 ph[4], pl[4];
                ph[0] = packbf(cs[2 * kk][0], cs[2 * kk][1]);
                ph[1] = packbf(cs[2 * kk][2], cs[2 * kk][3]);
                ph[2] = packbf(cs[2 * kk + 1][0], cs[2 * kk + 1][1]);
                ph[3] = packbf(cs[2 * kk + 1][2], cs[2 * kk + 1][3]);
                pl[0] = packbf(cs[2 * kk][0] - bf_lo_f(ph[0]),
                               cs[2 * kk][1] - bf_hi_f(ph[0]));
                pl[1] = packbf(cs[2 * kk][2] - bf_lo_f(ph[1]),
                               cs[2 * kk][3] - bf_hi_f(ph[1]));
                pl[2] = packbf(cs[2 * kk + 1][0] - bf_lo_f(ph[2]),
                               cs[2 * kk + 1][1] - bf_hi_f(ph[2]));
                pl[3] = packbf(cs[2 * kk + 1][2] - bf_lo_f(ph[3]),
                               cs[2 * kk + 1][3] - bf_hi_f(ph[3]));
                #pragma unroll
                for (int njp = 0; njp < 4; njp++) {
                    u32 vh0, vh1, vh2, vh3, vl0, vl1, vl2, vl3;
                    u32 va = voff + kk * (16 * FA_ROWB) + njp * 32;
                    ldsm4t(vh0, vh1, vh2, vh3, va);
                    ldsm4t(vl0, vl1, vl2, vl3, va + (FA_VL - FA_VH));
                    mma16(ob[mi][2 * njp],     ph[0], ph[1], ph[2], ph[3], vh0, vh1);
                    mma16(ob[mi][2 * njp + 1], ph[0], ph[1], ph[2], ph[3], vh2, vh3);
                    mma16(ob[mi][2 * njp],     pl[0], pl[1], pl[2], pl[3], vh0, vh1);
                    mma16(ob[mi][2 * njp + 1], pl[0], pl[1], pl[2], pl[3], vh2, vh3);
                    mma16(ob[mi][2 * njp],     ph[0], ph[1], ph[2], ph[3], vl0, vl1);
                    mma16(ob[mi][2 * njp + 1], ph[0], ph[1], ph[2], ph[3], vl2, vl3);
                }
            }
        }
        __syncthreads();
    }

    // epilogue: gate-scaled **fp16** hi/lo planes from O fragments
    u32* OH = f.OH[sel];
    u32* OL = f.OL[sel];
    #pragma unroll
    for (int mi = 0; mi < 2; mi++) {
        #pragma unroll
        for (int rr = 0; rr < 2; rr++) {
            int r = row0 + wid * 32 + mi * 16 + gq + rr * 8;
            float gv = G[r];
            float gs = (sel == 0) ? gv : (1.f - gv);
            float inv = gs / lrun[mi][rr];
            size_t obase = (size_t)r * 512 + h * 32;
            #pragma unroll
            for (int ni = 0; ni < 8; ni++) {
                float v0 = ob[mi][ni][rr * 2 + 0] * inv;
                float v1 = ob[mi][ni][rr * 2 + 1] * inv;
                __half2 hw = __floats2half2_rn(v0, v1);
                float l0 = v0 - __low2float(hw);
                float l1 = v1 - __high2float(hw);
                __half2 lw = __floats2half2_rn(l0, l1);
                OH[obase + 4 * ni + tq] = *(u32*)&hw;
                OL[obase + 4 * ni + tq] = *(u32*)&lw;
            }
        }
    }
}

// ---------------- gate: G[r] = sigmoid(H[r,:] . W2 + b2), one warp per row ----
__global__ __launch_bounds__(256)
void gate_kernel(const float* __restrict__ H, const float* __restrict__ W2,
                 const float* __restrict__ b2, float* __restrict__ G)
{
    int w = (blockIdx.x * blockDim.x + threadIdx.x) >> 5;
    int lane = threadIdx.x & 31;
    const float* hp = H + (size_t)w * 1024;
    float s = 0.f;
    #pragma unroll
    for (int i = 0; i < 32; i++) s += hp[lane + i * 32] * W2[lane + i * 32];
    #pragma unroll
    for (int o = 16; o; o >>= 1) s += __shfl_xor_sync(0xffffffffu, s, o);
    if (lane == 0) G[w] = 1.f / (1.f + __expf(-(s + b2[0])));
}

// ---------------- launch ----------------
extern "C" void kernel_launch(void* const* d_in, const int* in_sizes, int n_in,
                              void* d_out, int out_size)
{
    const float* trend  = (const float*)d_in[0];
    const float* detail = (const float*)d_in[1];
    const float* protoT = (const float*)d_in[2];
    const float* protoD = (const float*)d_in[3];
    const float* tWq = (const float*)d_in[4];  const float* tbq = (const float*)d_in[5];
    const float* tWk = (const float*)d_in[6];  const float* tbk = (const float*)d_in[7];
    const float* tWv = (const float*)d_in[8];  const float* tbv = (const float*)d_in[9];
    const float* tWo = (const float*)d_in[10]; const float* tbo = (const float*)d_in[11];
    const float* dWq = (const float*)d_in[12]; const float* dbq = (const float*)d_in[13];
    const float* dWk = (const float*)d_in[14]; const float* dbk = (const float*)d_in[15];
    const float* dWv = (const float*)d_in[16]; const float* dbv = (const float*)d_in[17];
    const float* dWo = (const float*)d_in[18]; const float* dbo = (const float*)d_in[19];
    const float* gW1 = (const float*)d_in[20]; const float* gb1 = (const float*)d_in[21];
    const float* gW2 = (const float*)d_in[22]; const float* gb2 = (const float*)d_in[23];
    float* out = (float*)d_out;

    #define SYM(T, v, s) T* v; cudaGetSymbolAddress((void**)&v, s)
    SYM(float, H,  g_H);    SYM(float, G,  g_gate);
    SYM(u16, QtH, g_QtH);   SYM(u16, QtL, g_QtL);
    SYM(u16, QdH, g_QdH);   SYM(u16, QdL, g_QdL);
    SYM(u16, KtH, g_KtH);   SYM(u16, KtL, g_KtL);
    SYM(u16, KdH, g_KdH);   SYM(u16, KdL, g_KdL);
    SYM(u16, VtH, g_VtH);   SYM(u16, VtL, g_VtL);
    SYM(u16, VdH, g_VdH);   SYM(u16, VdL, g_VdL);
    SYM(u16, trH, g_trH);   SYM(u16, trL, g_trL);
    SYM(u16, deH, g_deH);   SYM(u16, deL, g_deL);
    SYM(u16, pTH, g_pTH);   SYM(u16, pTL, g_pTL);
    SYM(u16, pDH, g_pDH);   SYM(u16, pDL, g_pDL);
    SYM(u16, ctH, g_ctH);   SYM(u16, ctL, g_ctL);
    SYM(u16, cdH, g_cdH);   SYM(u16, cdL, g_cdL);
    SYM(u16, wqtH, g_wqtH); SYM(u16, wqtL, g_wqtL);
    SYM(u16, wqdH, g_wqdH); SYM(u16, wqdL, g_wqdL);
    SYM(u16, wktH, g_wktH); SYM(u16, wktL, g_wktL);
    SYM(u16, wvtH, g_wvtH); SYM(u16, wvtL, g_wvtL);
    SYM(u16, wkdH, g_wkdH); SYM(u16, wkdL, g_wkdL);
    SYM(u16, wvdH, g_wvdH); SYM(u16, wvdL, g_wvdL);
    SYM(u16, woH, g_woH);
    SYM(u16, gw1H, g_gw1H); SYM(u16, gw1L, g_gw1L);
    #undef SYM

    cudaFuncSetAttribute(tgemm, cudaFuncAttributeMaxDynamicSharedMemorySize, SMEM_DYN);
    cudaFuncSetAttribute(flash_attn, cudaFuncAttributeMaxDynamicSharedMemorySize, FA_SMEM);

    // 0a) A-side conversions (bf16 hi/lo)
    {
        CArg c = {};
        c.src[0] = trend;  c.dH[0] = (u32*)trH; c.dL[0] = (u32*)trL; c.n2[0] = 4096 * 512;
        c.src[1] = detail; c.dH[1] = (u32*)deH; c.dL[1] = (u32*)deL; c.n2[1] = 4096 * 512;
        c.src[2] = protoT; c.dH[2] = (u32*)pTH; c.dL[2] = (u32*)pTL; c.n2[2] = 1000 * 2048;
        c.src[3] = protoD; c.dH[3] = (u32*)pDH; c.dL[3] = (u32*)pDL; c.n2[3] = 1000 * 2048;
        convA<<<dim3(8192, 4), 256>>>(c);
    }
    // 0b) weight transpose+split (Wo -> single fp16 plane)
    {
        TArg t = {};
        int i = 0;
        auto add = [&](const float* s, u16* h, u16* l, int K, int N, int ldk,
                       int koff, int f16) {
            t.src[i] = s; t.dH[i] = h; t.dL[i] = l;
            t.K[i] = K; t.N[i] = N; t.ldk[i] = ldk; t.koff[i] = koff;
            t.f16[i] = f16; i++;
        };
        add(tWq, wqtH, wqtL, 1024, 1024, 1024, 0, 0);
        add(dWq, wqdH, wqdL, 1024, 1024, 1024, 0, 0);
        add(tWk, wktH, wktL, 4096, 1024, 4096, 0, 0);
        add(tWv, wvtH, wvtL, 4096, 1024, 4096, 0, 0);
        add(dWk, wkdH, wkdL, 4096, 1024, 4096, 0, 0);
        add(dWv, wvdH, wvdL, 4096, 1024, 4096, 0, 0);
        add(tWo, woH,  nullptr, 1024, 4096, 2048, 0, 1);     // fp16 single
        add(dWo, woH,  nullptr, 1024, 4096, 2048, 1024, 1);  // fp16 single
        add(gW1, gw1H, gw1L, 2048, 1024, 2048, 0, 0);
        convB<<<dim3(128, 128, 9), dim3(32, 8)>>>(t);
    }

    // 1) merged pre-attention GEMMs (1024 CTAs, all bf16 3-term)
    {
        MArg a = {};
        int blk = 0, i = 0;
        auto seg = [&](const u16* ah, const u16* al, const u16* a2h, const u16* a2l,
                       const u16* bh, const u16* bl, const float* bi,
                       float* c, u16* ch, u16* cl,
                       int M, int N, int K, int ksp, int epi) {
            Seg& s = a.s[i++];
            s.AH = ah; s.AL = al; s.A2H = a2h; s.A2L = a2l; s.BH = bh; s.BL = bl;
            s.bias = bi; s.bias2 = nullptr; s.C = c; s.CH = ch; s.CL = cl;
            s.M = M; s.N = N; s.K = K; s.Ksp = ksp; s.epi = epi; s.fmt = 0;
            s.gx = N / 128; s.blk0 = blk;
            blk += (N / 128) * ((M + 127) / 128);
        };
        seg(trH, trL, deH, deL, gw1H, gw1L, gb1, H, nullptr, nullptr,
            4096, 1024, 2048, 1024, 1);
        seg(trH, trL, trH, trL, wqtH, wqtL, tbq, nullptr, QtH, QtL,
            4096, 1024, 1024, 1024, 2);
        seg(deH, deL, deH, deL, wqdH, wqdL, dbq, nullptr, QdH, QdL,
            4096, 1024, 1024, 1024, 2);
        seg(pTH, pTL, pTH, pTL, wktH, wktL, tbk, nullptr, KtH, KtL,
            1000, 1024, 4096, 4096, 2);
        seg(pTH, pTL, pTH, pTL, wvtH, wvtL, tbv, nullptr, VtH, VtL,
            1000, 1024, 4096, 4096, 2);
        seg(pDH, pDL, pDH, pDL, wkdH, wkdL, dbk, nullptr, KdH, KdL,
            1000, 1024, 4096, 4096, 2);
        seg(pDH, pDL, pDH, pDL, wvdH, wvdL, dbv, nullptr, VdH, VdL,
            1000, 1024, 4096, 4096, 2);
        a.nseg = i;
        a.gate = G;
        tgemm<<<blk, 256, SMEM_DYN>>>(a);
    }
    // 2) gate
    gate_kernel<<<512, 256>>>(H, gW2, gb2, G);

    // 3) attention (full-MMA; gate-scaled fp16 hi/lo output)
    {
        FArg fa = {};
        fa.QH[0] = QtH; fa.QL[0] = QtL; fa.KH[0] = KtH; fa.KL[0] = KtL;
        fa.VH[0] = VtH; fa.VL[0] = VtL;
        fa.OH[0] = (u32*)ctH; fa.OL[0] = (u32*)ctL;
        fa.QH[1] = QdH; fa.QL[1] = QdL; fa.KH[1] = KdH; fa.KL[1] = KdL;
        fa.VH[1] = VdH; fa.VL[1] = VdL;
        fa.OH[1] = (u32*)cdH; fa.OL[1] = (u32*)cdL;
        flash_attn<<<dim3(4, 16, 16), 128, FA_SMEM>>>(fa, 1000, G);
    }
    // 4) merged output projection + blend (fp16 2-term, epi 4)
    {
        MArg a = {};
        Seg& s = a.s[0];
        s.AH = ctH; s.AL = ctL; s.A2H = cdH; s.A2L = cdL;
        s.BH = woH; s.BL = nullptr;
        s.bias = tbo; s.bias2 = dbo; s.C = out; s.CH = nullptr; s.CL = nullptr;
        s.M = 4096; s.N = 4096; s.K = 2048; s.Ksp = 1024; s.epi = 4; s.fmt = 1;
        s.gx = 32; s.blk0 = 0;
        a.nseg = 1;
        a.gate = G;
        tgemm<<<1024, 256, SMEM_DYN>>>(a);
    }

    (void)in_sizes; (void)n_in; (void)out_size;
}